// round 8
// baseline (speedup 1.0000x reference)
#include <cuda_runtime.h>
#include <math.h>
#include <stdint.h>

// ---------------- problem constants ----------------
constexpr int   Bb   = 2;
constexpr int   Ss   = 2048;
constexpr int   Ee   = 1024;
constexpr int   Hh   = 16;
constexpr int   Dd   = 64;
constexpr int   Ff   = 4096;
constexpr int   Mtok = Bb * Ss;
constexpr float EPSc  = 1e-5f;
constexpr float SCALE = 0.125f;

// ---------------- scratch ----------------
__device__ float g_nx  [(size_t)Mtok * Ee];
__device__ float g_q   [(size_t)Mtok * Ee];   // [B,H,S,D]
__device__ float g_k   [(size_t)Mtok * Ee];   // [B,H,S,D]
__device__ float g_v   [(size_t)Mtok * Ee];   // [B,H,D,S]  (transposed)
__device__ float g_vals[(size_t)Mtok * Ee];   // [B,S,E]
__device__ float g_x1  [(size_t)Mtok * Ee];
__device__ float g_h   [(size_t)Mtok * Ff];
// tf32-rounded weight copies (rebuilt every call; deterministic)
__device__ float g_wqkv[(size_t)3 * Ee * Ee];
__device__ float g_bqkv[3 * Ee];
__device__ float g_wo  [(size_t)Ee * Ee];
__device__ float g_w1  [(size_t)Ff * Ee];
__device__ float g_w2  [(size_t)Ee * Ff];

// ---------------- tf32 helpers ----------------
__device__ __forceinline__ float to_tf32(float x) {
    float r; asm("cvt.rna.tf32.f32 %0, %1;" : "=f"(r) : "f"(x)); return r;
}
__device__ __forceinline__ void ldsm4(uint32_t& r0, uint32_t& r1, uint32_t& r2, uint32_t& r3,
                                      const float* p) {
    uint32_t a = (uint32_t)__cvta_generic_to_shared(p);
    asm volatile("ldmatrix.sync.aligned.m8n8.x4.shared.b16 {%0,%1,%2,%3}, [%4];"
                 : "=r"(r0), "=r"(r1), "=r"(r2), "=r"(r3) : "r"(a));
}
__device__ __forceinline__ void mma_tf32(float* c, const uint32_t* a, const uint32_t* b) {
    asm volatile("mma.sync.aligned.m16n8k8.row.col.f32.tf32.tf32.f32 "
                 "{%0,%1,%2,%3}, {%4,%5,%6,%7}, {%8,%9}, {%0,%1,%2,%3};"
                 : "+f"(c[0]), "+f"(c[1]), "+f"(c[2]), "+f"(c[3])
                 : "r"(a[0]), "r"(a[1]), "r"(a[2]), "r"(a[3]), "r"(b[0]), "r"(b[1]));
}
__device__ __forceinline__ void cp16(float* smem_dst, const float* gmem_src) {
    uint32_t a = (uint32_t)__cvta_generic_to_shared(smem_dst);
    asm volatile("cp.async.cg.shared.global [%0], [%1], 16;" :: "r"(a), "l"(gmem_src));
}
__device__ __forceinline__ void cp_commit() { asm volatile("cp.async.commit_group;"); }
template<int N> __device__ __forceinline__ void cp_wait() {
    asm volatile("cp.async.wait_group %0;" :: "n"(N));
}

// ---------------- weight rounding / packing (per call; ~15us total) ----------------
__global__ void pack_qkv_w(const float* __restrict__ wq, const float* __restrict__ wk,
                           const float* __restrict__ wv, float* __restrict__ dst)
{
    const int row = blockIdx.x;  // 0..3071
    const float* src = (row < Ee)     ? wq + (size_t)row * Ee
                     : (row < 2 * Ee) ? wk + (size_t)(row - Ee) * Ee
                                      : wv + (size_t)(row - 2 * Ee) * Ee;
    float4 v = ((const float4*)src)[threadIdx.x];
    ((float4*)(dst + (size_t)row * Ee))[threadIdx.x] =
        make_float4(to_tf32(v.x), to_tf32(v.y), to_tf32(v.z), to_tf32(v.w));
}
__global__ void pack_qkv_b(const float* __restrict__ bq, const float* __restrict__ bk,
                           const float* __restrict__ bv, float* __restrict__ dst)
{
    const float* s = blockIdx.x == 0 ? bq : blockIdx.x == 1 ? bk : bv;
    dst[blockIdx.x * Ee + threadIdx.x] = s[threadIdx.x];
}
__global__ void round_copy(const float* __restrict__ src, float* __restrict__ dst)
{
    size_t i = (size_t)blockIdx.x * blockDim.x + threadIdx.x;
    float4 v = ((const float4*)src)[i];
    ((float4*)dst)[i] = make_float4(to_tf32(v.x), to_tf32(v.y), to_tf32(v.z), to_tf32(v.w));
}

// ---------------- reductions ----------------
__device__ __forceinline__ float warpSum(float v) {
    #pragma unroll
    for (int o = 16; o; o >>= 1) v += __shfl_xor_sync(0xFFFFFFFFu, v, o);
    return v;
}
__device__ __forceinline__ float blockSum(float v, float* sh, float* bc) {
    int lane = threadIdx.x & 31, wid = threadIdx.x >> 5;
    v = warpSum(v);
    if (!lane) sh[wid] = v;
    __syncthreads();
    if (wid == 0) {
        v = (lane < 8) ? sh[lane] : 0.f;
        v = warpSum(v);
        if (!lane) *bc = v;
    }
    __syncthreads();
    return *bc;
}

// ---------------- LayerNorm (output rounded to tf32 — only feeds GEMMs) ----------------
__global__ void ln_kernel(const float* __restrict__ x, const float* __restrict__ w,
                          const float* __restrict__ b, float* __restrict__ out)
{
    __shared__ float sh[32];
    __shared__ float bc;
    const int row = blockIdx.x, t = threadIdx.x;
    float4 v = *(const float4*)(x + (size_t)row * Ee + t * 4);
    float mean = blockSum(v.x + v.y + v.z + v.w, sh, &bc) * (1.f / Ee);
    float dx0 = v.x - mean, dx1 = v.y - mean, dx2 = v.z - mean, dx3 = v.w - mean;
    float var = blockSum(dx0*dx0 + dx1*dx1 + dx2*dx2 + dx3*dx3, sh, &bc) * (1.f / (Ee - 1));
    float r = 1.f / (sqrtf(var) + EPSc);
    float4 wv = *(const float4*)(w + t * 4);
    float4 bv = *(const float4*)(b + t * 4);
    float4 o;
    o.x = to_tf32(wv.x * dx0 * r + bv.x);
    o.y = to_tf32(wv.y * dx1 * r + bv.y);
    o.z = to_tf32(wv.z * dx2 * r + bv.z);
    o.w = to_tf32(wv.w * dx3 * r + bv.w);
    *(float4*)(out + (size_t)row * Ee + t * 4) = o;
}

// ---------------- flash attention: Br=64, Bc=64, 4 warps (inputs pre-rounded) ----------------
constexpr int FLD = 68;

__global__ void __launch_bounds__(128)
flash_kernel(const float* __restrict__ q, const float* __restrict__ k,
             const float* __restrict__ v, const int* __restrict__ mask,
             float* __restrict__ vals)
{
    extern __shared__ float sm[];
    float* Ksm = sm;
    float* Vsm = Ksm + 64 * FLD;
    float* Psm = Vsm + 64 * FLD;

    const int bh = blockIdx.y;
    const int b_ = bh >> 4, h_ = bh & 15;
    const int q0 = blockIdx.x * 64;
    const int tid = threadIdx.x, lane = tid & 31, w = tid >> 5;
    const int mi = lane >> 3, rr = lane & 7;

    const float* Qp = q + ((size_t)bh * Ss + q0) * Dd;
    const float* Kp = k + (size_t)bh * Ss * Dd;
    const float* Vp = v + (size_t)bh * Dd * Ss;

    #pragma unroll
    for (int i = tid; i < 64 * 16; i += 128) {
        int r = i >> 4, c4 = (i & 15) << 2;
        *(float4*)&Psm[r * FLD + c4] = *(const float4*)(Qp + (size_t)r * Dd + c4);
    }
    __syncthreads();
    uint32_t qa[8][4];
    #pragma unroll
    for (int ks = 0; ks < 8; ks++) {
        const float* p = &Psm[(w*16 + (mi & 1)*8 + rr) * FLD + ks*8 + ((mi >> 1) & 1)*4];
        ldsm4(qa[ks][0], qa[ks][1], qa[ks][2], qa[ks][3], p);
    }

    float oacc[8][4];
    #pragma unroll
    for (int i = 0; i < 8; i++)
        #pragma unroll
        for (int j = 0; j < 4; j++) oacc[i][j] = 0.f;
    float mrun0 = -1e30f, mrun1 = -1e30f, lrun0 = 0.f, lrun1 = 0.f;

    const int r0 = q0 + w*16 + (lane >> 2);
    const int* mrow0 = mask + ((size_t)b_ * Ss + r0) * Ss;
    const int* mrow1 = mrow0 + 8 * (size_t)Ss;

    for (int it = 0; it < Ss / 64; it++) {
        const int kv0 = it * 64;
        #pragma unroll
        for (int i = tid; i < 64 * 16; i += 128) {
            int r = i >> 4, c4 = (i & 15) << 2;
            *(float4*)&Ksm[r * FLD + c4] = *(const float4*)(Kp + (size_t)(kv0 + r) * Dd + c4);
        }
        #pragma unroll
        for (int i = tid; i < 64 * 16; i += 128) {
            int r = i >> 4, c4 = (i & 15) << 2;
            *(float4*)&Vsm[r * FLD + c4] = *(const float4*)(Vp + (size_t)r * Ss + kv0 + c4);
        }
        __syncthreads();

        float sacc[8][4];
        #pragma unroll
        for (int i = 0; i < 8; i++)
            #pragma unroll
            for (int j = 0; j < 4; j++) sacc[i][j] = 0.f;
        #pragma unroll
        for (int ks = 0; ks < 8; ks++) {
            uint32_t bf[8][2];
            #pragma unroll
            for (int pq = 0; pq < 4; pq++) {
                const float* p = &Ksm[(pq*16 + ((mi >> 1) & 1)*8 + rr) * FLD + ks*8 + (mi & 1)*4];
                ldsm4(bf[2*pq][0], bf[2*pq][1], bf[2*pq+1][0], bf[2*pq+1][1], p);
            }
            #pragma unroll
            for (int nt = 0; nt < 8; nt++) mma_tf32(sacc[nt], qa[ks], bf[nt]);
        }

        float ml0 = -1e30f, ml1 = -1e30f;
        #pragma unroll
        for (int nt = 0; nt < 8; nt++) {
            int c = kv0 + nt*8 + (lane & 3)*2;
            int2 ma = *(const int2*)(mrow0 + c);
            int2 mb = *(const int2*)(mrow1 + c);
            sacc[nt][0] = ma.x ? sacc[nt][0] * SCALE : -1e30f;
            sacc[nt][1] = ma.y ? sacc[nt][1] * SCALE : -1e30f;
            sacc[nt][2] = mb.x ? sacc[nt][2] * SCALE : -1e30f;
            sacc[nt][3] = mb.y ? sacc[nt][3] * SCALE : -1e30f;
            ml0 = fmaxf(ml0, fmaxf(sacc[nt][0], sacc[nt][1]));
            ml1 = fmaxf(ml1, fmaxf(sacc[nt][2], sacc[nt][3]));
        }
        ml0 = fmaxf(ml0, __shfl_xor_sync(0xFFFFFFFFu, ml0, 1));
        ml0 = fmaxf(ml0, __shfl_xor_sync(0xFFFFFFFFu, ml0, 2));
        ml1 = fmaxf(ml1, __shfl_xor_sync(0xFFFFFFFFu, ml1, 1));
        ml1 = fmaxf(ml1, __shfl_xor_sync(0xFFFFFFFFu, ml1, 2));
        float mn0 = fmaxf(mrun0, ml0), mn1 = fmaxf(mrun1, ml1);
        float f0 = __expf(mrun0 - mn0), f1 = __expf(mrun1 - mn1);
        float ps0 = 0.f, ps1 = 0.f;
        #pragma unroll
        for (int nt = 0; nt < 8; nt++) {
            sacc[nt][0] = __expf(sacc[nt][0] - mn0);
            sacc[nt][1] = __expf(sacc[nt][1] - mn0);
            sacc[nt][2] = __expf(sacc[nt][2] - mn1);
            sacc[nt][3] = __expf(sacc[nt][3] - mn1);
            ps0 += sacc[nt][0] + sacc[nt][1];
            ps1 += sacc[nt][2] + sacc[nt][3];
        }
        ps0 += __shfl_xor_sync(0xFFFFFFFFu, ps0, 1);
        ps0 += __shfl_xor_sync(0xFFFFFFFFu, ps0, 2);
        ps1 += __shfl_xor_sync(0xFFFFFFFFu, ps1, 1);
        ps1 += __shfl_xor_sync(0xFFFFFFFFu, ps1, 2);
        lrun0 = lrun0 * f0 + ps0; lrun1 = lrun1 * f1 + ps1;
        mrun0 = mn0; mrun1 = mn1;
        #pragma unroll
        for (int nt = 0; nt < 8; nt++) {
            oacc[nt][0] *= f0; oacc[nt][1] *= f0;
            oacc[nt][2] *= f1; oacc[nt][3] *= f1;
        }
        {
            int pr = w*16 + (lane >> 2);
            #pragma unroll
            for (int nt = 0; nt < 8; nt++) {
                int c = nt*8 + (lane & 3)*2;
                *(float2*)&Psm[pr * FLD + c] =
                    make_float2(to_tf32(sacc[nt][0]), to_tf32(sacc[nt][1]));
                *(float2*)&Psm[(pr + 8) * FLD + c] =
                    make_float2(to_tf32(sacc[nt][2]), to_tf32(sacc[nt][3]));
            }
        }
        __syncthreads();

        #pragma unroll
        for (int ks = 0; ks < 8; ks++) {
            uint32_t pa[4];
            {
                const float* p = &Psm[(w*16 + (mi & 1)*8 + rr) * FLD + ks*8 + ((mi >> 1) & 1)*4];
                ldsm4(pa[0], pa[1], pa[2], pa[3], p);
            }
            uint32_t bf[8][2];
            #pragma unroll
            for (int pq = 0; pq < 4; pq++) {
                const float* p = &Vsm[(pq*16 + ((mi >> 1) & 1)*8 + rr) * FLD + ks*8 + (mi & 1)*4];
                ldsm4(bf[2*pq][0], bf[2*pq][1], bf[2*pq+1][0], bf[2*pq+1][1], p);
            }
            #pragma unroll
            for (int nt = 0; nt < 8; nt++) mma_tf32(oacc[nt], pa, bf[nt]);
        }
        __syncthreads();
    }

    // normalize, round (vals only feeds the O-proj GEMM), write
    float inv0 = 1.f / lrun0, inv1 = 1.f / lrun1;
    float* op = vals + ((size_t)b_ * Ss + r0) * Ee + h_ * Dd;
    #pragma unroll
    for (int nt = 0; nt < 8; nt++) {
        int c = nt*8 + (lane & 3)*2;
        *(float2*)(op + c) =
            make_float2(to_tf32(oacc[nt][0] * inv0), to_tf32(oacc[nt][1] * inv0));
        *(float2*)(op + (size_t)8 * Ee + c) =
            make_float2(to_tf32(oacc[nt][2] * inv1), to_tf32(oacc[nt][3] * inv1));
    }
}

// ---------------- tf32 dense GEMM, 3-stage cp.async, inputs pre-rounded ----------------
// C[m,n] = sum_k A[m,k] * B[n,k]; B is [N,K] row-major.
// EPI: 1=bias+relu+round, 2=bias+residual, 6=bias+QKV scatter (N=3072)
constexpr int GBM = 128, GBN = 128, GBK = 16, GLD = 20, STAGES = 3;
constexpr int STAGE_F = GBM * GLD;                 // floats per stage (A or B): 2560
constexpr int GEMM_SMEM = 2 * STAGES * STAGE_F * 4; // 61440 bytes

template<int EPI>
__global__ void __launch_bounds__(512, 1)
gemm_tf32(const float* __restrict__ A, const float* __restrict__ Bm,
          const float* __restrict__ bias, const float* __restrict__ Res,
          float* __restrict__ C, int M, int N, int K)
{
    extern __shared__ float sm[];
    const int tid = threadIdx.x, lane = tid & 31, warp = tid >> 5;
    const int wm = warp >> 2, wn = warp & 3;
    const int rowBase = blockIdx.y * GBM, colBase = blockIdx.x * GBN;
    const int lr = tid >> 2, lc = (tid & 3) << 2;   // loader: row, col4

    const float* Ag = A  + (size_t)(rowBase + lr) * K + lc;
    const float* Bg = Bm + (size_t)(colBase + lr) * K + lc;

    float acc[2][4][4];
    #pragma unroll
    for (int i = 0; i < 2; i++)
        #pragma unroll
        for (int j = 0; j < 4; j++)
            #pragma unroll
            for (int l = 0; l < 4; l++) acc[i][j][l] = 0.f;

    const int ntk = K / GBK;

    #pragma unroll
    for (int s = 0; s < STAGES; s++) {
        cp16(sm + s * STAGE_F + lr * GLD + lc, Ag + s * GBK);
        cp16(sm + (STAGES + s) * STAGE_F + lr * GLD + lc, Bg + s * GBK);
        cp_commit();
    }

    const int mi = lane >> 3, rr = lane & 7;

    for (int kt = 0; kt < ntk; kt++) {
        cp_wait<STAGES - 1>();
        __syncthreads();
        const int buf = kt % STAGES;
        const float* Asb = sm + buf * STAGE_F;
        const float* Bsb = sm + (STAGES + buf) * STAGE_F;
        #pragma unroll
        for (int ks = 0; ks < 2; ks++) {
            const int ko = ks * 8;
            uint32_t a[2][4], b[4][2];
            #pragma unroll
            for (int mt = 0; mt < 2; mt++) {
                const float* p = &Asb[(wm*32 + mt*16 + (mi & 1)*8 + rr) * GLD + ko + ((mi >> 1) & 1)*4];
                ldsm4(a[mt][0], a[mt][1], a[mt][2], a[mt][3], p);
            }
            #pragma unroll
            for (int pq = 0; pq < 2; pq++) {
                const float* p = &Bsb[(wn*32 + pq*16 + ((mi >> 1) & 1)*8 + rr) * GLD + ko + (mi & 1)*4];
                ldsm4(b[2*pq][0], b[2*pq][1], b[2*pq+1][0], b[2*pq+1][1], p);
            }
            #pragma unroll
            for (int mt = 0; mt < 2; mt++)
                #pragma unroll
                for (int nt = 0; nt < 4; nt++)
                    mma_tf32(acc[mt][nt], a[mt], b[nt]);
        }
        __syncthreads();
        const int nxt = kt + STAGES;
        if (nxt < ntk) {
            cp16(sm + buf * STAGE_F + lr * GLD + lc, Ag + nxt * GBK);
            cp16(sm + (STAGES + buf) * STAGE_F + lr * GLD + lc, Bg + nxt * GBK);
        }
        cp_commit();
    }

    // ---- epilogue ----
    #pragma unroll
    for (int mt = 0; mt < 2; mt++)
        #pragma unroll
        for (int half = 0; half < 2; half++) {
            const int row = rowBase + wm*32 + mt*16 + (lane >> 2) + half*8;
            #pragma unroll
            for (int nt = 0; nt < 4; nt++) {
                const int col = colBase + wn*32 + nt*8 + (lane & 3)*2;
                float v0 = acc[mt][nt][half*2 + 0];
                float v1 = acc[mt][nt][half*2 + 1];
                float2 bb = *(const float2*)(bias + col);
                v0 += bb.x; v1 += bb.y;
                if constexpr (EPI == 1) {
                    v0 = to_tf32(fmaxf(v0, 0.f)); v1 = to_tf32(fmaxf(v1, 0.f));
                    *(float2*)(C + (size_t)row * N + col) = make_float2(v0, v1);
                } else if constexpr (EPI == 2) {
                    float2 r2 = *(const float2*)(Res + (size_t)row * N + col);
                    *(float2*)(C + (size_t)row * N + col) = make_float2(v0 + r2.x, v1 + r2.y);
                } else { // EPI == 6: QKV scatter; C unused, fixed targets
                    int b_ = row / Ss, s_ = row - b_ * Ss;
                    v0 = to_tf32(v0); v1 = to_tf32(v1);
                    if (col < Ee) {
                        int h_ = col >> 6, d_ = col & 63;
                        *(float2*)(g_q + (((size_t)b_ * Hh + h_) * Ss + s_) * Dd + d_) = make_float2(v0, v1);
                    } else if (col < 2 * Ee) {
                        int c2 = col - Ee, h_ = c2 >> 6, d_ = c2 & 63;
                        *(float2*)(g_k + (((size_t)b_ * Hh + h_) * Ss + s_) * Dd + d_) = make_float2(v0, v1);
                    } else {
                        int c2 = col - 2 * Ee, h_ = c2 >> 6, d_ = c2 & 63;
                        float* pp = g_v + (((size_t)b_ * Hh + h_) * Dd + d_) * Ss + s_;
                        pp[0]  = v0;
                        pp[Ss] = v1;
                    }
                }
            }
        }
}

// ---------------- orchestration ----------------
extern "C" void kernel_launch(void* const* d_in, const int* in_sizes, int n_in,
                              void* d_out, int out_size)
{
    const float* x    = (const float*)d_in[0];
    const int*   mask = (const int*)  d_in[1];
    const float* wq   = (const float*)d_in[2];
    const float* bq   = (const float*)d_in[3];
    const float* wk   = (const float*)d_in[4];
    const float* bk   = (const float*)d_in[5];
    const float* wv   = (const float*)d_in[6];
    const float* bv   = (const float*)d_in[7];
    const float* wo   = (const float*)d_in[8];
    const float* bo   = (const float*)d_in[9];
    const float* w1   = (const float*)d_in[10];
    const float* b1   = (const float*)d_in[11];
    const float* w2   = (const float*)d_in[12];
    const float* b2   = (const float*)d_in[13];
    const float* ln1w = (const float*)d_in[14];
    const float* ln1b = (const float*)d_in[15];
    const float* ln2w = (const float*)d_in[16];
    const float* ln2b = (const float*)d_in[17];
    float* out = (float*)d_out;

    float *nx, *q, *k, *v, *vals, *x1, *hbuf, *wqkv, *bqkv, *rwo, *rw1, *rw2;
    cudaGetSymbolAddress((void**)&nx,   g_nx);
    cudaGetSymbolAddress((void**)&q,    g_q);
    cudaGetSymbolAddress((void**)&k,    g_k);
    cudaGetSymbolAddress((void**)&v,    g_v);
    cudaGetSymbolAddress((void**)&vals, g_vals);
    cudaGetSymbolAddress((void**)&x1,   g_x1);
    cudaGetSymbolAddress((void**)&hbuf, g_h);
    cudaGetSymbolAddress((void**)&wqkv, g_wqkv);
    cudaGetSymbolAddress((void**)&bqkv, g_bqkv);
    cudaGetSymbolAddress((void**)&rwo,  g_wo);
    cudaGetSymbolAddress((void**)&rw1,  g_w1);
    cudaGetSymbolAddress((void**)&rw2,  g_w2);

    const int flash_smem = 3 * 64 * FLD * sizeof(float);
    cudaFuncSetAttribute(flash_kernel, cudaFuncAttributeMaxDynamicSharedMemorySize, flash_smem);
    cudaFuncSetAttribute(gemm_tf32<1>, cudaFuncAttributeMaxDynamicSharedMemorySize, GEMM_SMEM);
    cudaFuncSetAttribute(gemm_tf32<2>, cudaFuncAttributeMaxDynamicSharedMemorySize, GEMM_SMEM);
    cudaFuncSetAttribute(gemm_tf32<6>, cudaFuncAttributeMaxDynamicSharedMemorySize, GEMM_SMEM);

    // 0. round/pack weights (independent of data path; overlaps nothing but is tiny)
    pack_qkv_w<<<3 * Ee, 256>>>(wq, wk, wv, wqkv);
    pack_qkv_b<<<3, Ee>>>(bq, bk, bv, bqkv);
    round_copy<<<(Ee * Ee) / 1024, 256>>>(wo, rwo);
    round_copy<<<(Ff * Ee) / 1024, 256>>>(w1, rw1);
    round_copy<<<(Ee * Ff) / 1024, 256>>>(w2, rw2);

    // 1. LN1 (tf32-rounded output)
    ln_kernel<<<Mtok, 256>>>(x, ln1w, ln1b, nx);

    // 2. fused QKV projection -> q,k,v (v transposed), rounded
    {
        dim3 g(3 * Ee / GBN, Mtok / GBM);
        gemm_tf32<6><<<g, 512, GEMM_SMEM>>>(nx, wqkv, bqkv, nullptr, nullptr, Mtok, 3 * Ee, Ee);
    }

    // 3. flash attention -> vals (rounded)
    {
        dim3 g(Ss / 64, Bb * Hh);
        flash_kernel<<<g, 128, flash_smem>>>(q, k, v, mask, vals);
    }

    // 4. O projection + residual -> x1 (fp32)
    {
        dim3 g(Ee / GBN, Mtok / GBM);
        gemm_tf32<2><<<g, 512, GEMM_SMEM>>>(vals, rwo, bo, x, x1, Mtok, Ee, Ee);
    }

    // 5. LN2 (rounded)
    ln_kernel<<<Mtok, 256>>>(x1, ln2w, ln2b, nx);

    // 6. FFN1: relu, rounded -> hbuf
    {
        dim3 g(Ff / GBN, Mtok / GBM);
        gemm_tf32<1><<<g, 512, GEMM_SMEM>>>(nx, rw1, b1, nullptr, hbuf, Mtok, Ff, Ee);
    }

    // 7. FFN2 + residual -> out (fp32)
    {
        dim3 g(Ee / GBN, Mtok / GBM);
        gemm_tf32<2><<<g, 512, GEMM_SMEM>>>(hbuf, rw2, b2, x1, out, Mtok, Ee, Ff);
    }
}

// round 12
// speedup vs baseline: 1.5707x; 1.5707x over previous
#include <cuda_runtime.h>
#include <math.h>
#include <stdint.h>

// ---------------- problem constants ----------------
constexpr int   Bb   = 2;
constexpr int   Ss   = 2048;
constexpr int   Ee   = 1024;
constexpr int   Hh   = 16;
constexpr int   Dd   = 64;
constexpr int   Ff   = 4096;
constexpr int   Mtok = Bb * Ss;
constexpr float EPSc  = 1e-5f;
constexpr float SCALE = 0.125f;

// ---------------- scratch ----------------
__device__ float g_nx  [(size_t)Mtok * Ee];
__device__ float g_q   [(size_t)Mtok * Ee];   // [B,H,S,D]
__device__ float g_k   [(size_t)Mtok * Ee];   // [B,H,S,D]
__device__ float g_v   [(size_t)Mtok * Ee];   // [B,H,D,S]  (transposed)
__device__ float g_vals[(size_t)Mtok * Ee];   // [B,S,E]
__device__ float g_x1  [(size_t)Mtok * Ee];
__device__ float g_h   [(size_t)Mtok * Ff];
__device__ float g_wqkv[(size_t)3 * Ee * Ee]; // packed [3072,1024] (raw copy)
__device__ float g_bqkv[3 * Ee];

// ---------------- tf32 helpers ----------------
__device__ __forceinline__ float to_tf32(float x) {
    float r; asm("cvt.rna.tf32.f32 %0, %1;" : "=f"(r) : "f"(x)); return r;
}
__device__ __forceinline__ void ldsm4(uint32_t& r0, uint32_t& r1, uint32_t& r2, uint32_t& r3,
                                      const float* p) {
    uint32_t a = (uint32_t)__cvta_generic_to_shared(p);
    asm volatile("ldmatrix.sync.aligned.m8n8.x4.shared.b16 {%0,%1,%2,%3}, [%4];"
                 : "=r"(r0), "=r"(r1), "=r"(r2), "=r"(r3) : "r"(a));
}
__device__ __forceinline__ void mma_tf32(float* c, const uint32_t* a, const uint32_t* b) {
    asm volatile("mma.sync.aligned.m16n8k8.row.col.f32.tf32.tf32.f32 "
                 "{%0,%1,%2,%3}, {%4,%5,%6,%7}, {%8,%9}, {%0,%1,%2,%3};"
                 : "+f"(c[0]), "+f"(c[1]), "+f"(c[2]), "+f"(c[3])
                 : "r"(a[0]), "r"(a[1]), "r"(a[2]), "r"(a[3]), "r"(b[0]), "r"(b[1]));
}

// ---------------- pack kernels (raw copies, no rounding) ----------------
__global__ void pack_qkv_w(const float* __restrict__ wq, const float* __restrict__ wk,
                           const float* __restrict__ wv, float* __restrict__ dst)
{
    const int row = blockIdx.x;  // 0..3071
    const float* src = (row < Ee)     ? wq + (size_t)row * Ee
                     : (row < 2 * Ee) ? wk + (size_t)(row - Ee) * Ee
                                      : wv + (size_t)(row - 2 * Ee) * Ee;
    ((float4*)(dst + (size_t)row * Ee))[threadIdx.x] = ((const float4*)src)[threadIdx.x];
}
__global__ void pack_qkv_b(const float* __restrict__ bq, const float* __restrict__ bk,
                           const float* __restrict__ bv, float* __restrict__ dst)
{
    const float* s = blockIdx.x == 0 ? bq : blockIdx.x == 1 ? bk : bv;
    dst[blockIdx.x * Ee + threadIdx.x] = s[threadIdx.x];
}

// ---------------- reductions ----------------
__device__ __forceinline__ float warpSum(float v) {
    #pragma unroll
    for (int o = 16; o; o >>= 1) v += __shfl_xor_sync(0xFFFFFFFFu, v, o);
    return v;
}
__device__ __forceinline__ float blockSum(float v, float* sh, float* bc) {
    int lane = threadIdx.x & 31, wid = threadIdx.x >> 5;
    v = warpSum(v);
    if (!lane) sh[wid] = v;
    __syncthreads();
    if (wid == 0) {
        v = (lane < 8) ? sh[lane] : 0.f;
        v = warpSum(v);
        if (!lane) *bc = v;
    }
    __syncthreads();
    return *bc;
}

// ---------------- LayerNorm ----------------
__global__ void ln_kernel(const float* __restrict__ x, const float* __restrict__ w,
                          const float* __restrict__ b, float* __restrict__ out)
{
    __shared__ float sh[32];
    __shared__ float bc;
    const int row = blockIdx.x, t = threadIdx.x;
    float4 v = *(const float4*)(x + (size_t)row * Ee + t * 4);
    float mean = blockSum(v.x + v.y + v.z + v.w, sh, &bc) * (1.f / Ee);
    float dx0 = v.x - mean, dx1 = v.y - mean, dx2 = v.z - mean, dx3 = v.w - mean;
    float var = blockSum(dx0*dx0 + dx1*dx1 + dx2*dx2 + dx3*dx3, sh, &bc) * (1.f / (Ee - 1));
    float r = 1.f / (sqrtf(var) + EPSc);
    float4 wv = *(const float4*)(w + t * 4);
    float4 bv = *(const float4*)(b + t * 4);
    float4 o;
    o.x = wv.x * dx0 * r + bv.x;
    o.y = wv.y * dx1 * r + bv.y;
    o.z = wv.z * dx2 * r + bv.z;
    o.w = wv.w * dx3 * r + bv.w;
    *(float4*)(out + (size_t)row * Ee + t * 4) = o;
}

// ---------------- flash attention: Br=64, Bc=64, 4 warps (R7 verbatim) ----------------
constexpr int FLD = 68;

__global__ void __launch_bounds__(128)
flash_kernel(const float* __restrict__ q, const float* __restrict__ k,
             const float* __restrict__ v, const int* __restrict__ mask,
             float* __restrict__ vals)
{
    extern __shared__ float sm[];
    float* Ksm = sm;
    float* Vsm = Ksm + 64 * FLD;
    float* Psm = Vsm + 64 * FLD;

    const int bh = blockIdx.y;
    const int b_ = bh >> 4, h_ = bh & 15;
    const int q0 = blockIdx.x * 64;
    const int tid = threadIdx.x, lane = tid & 31, w = tid >> 5;
    const int mi = lane >> 3, rr = lane & 7;

    const float* Qp = q + ((size_t)bh * Ss + q0) * Dd;
    const float* Kp = k + (size_t)bh * Ss * Dd;
    const float* Vp = v + (size_t)bh * Dd * Ss;

    #pragma unroll
    for (int i = tid; i < 64 * 16; i += 128) {
        int r = i >> 4, c4 = (i & 15) << 2;
        float4 t = *(const float4*)(Qp + (size_t)r * Dd + c4);
        *(float4*)&Psm[r * FLD + c4] =
            make_float4(to_tf32(t.x), to_tf32(t.y), to_tf32(t.z), to_tf32(t.w));
    }
    __syncthreads();
    uint32_t qa[8][4];
    #pragma unroll
    for (int ks = 0; ks < 8; ks++) {
        const float* p = &Psm[(w*16 + (mi & 1)*8 + rr) * FLD + ks*8 + ((mi >> 1) & 1)*4];
        ldsm4(qa[ks][0], qa[ks][1], qa[ks][2], qa[ks][3], p);
    }

    float oacc[8][4];
    #pragma unroll
    for (int i = 0; i < 8; i++)
        #pragma unroll
        for (int j = 0; j < 4; j++) oacc[i][j] = 0.f;
    float mrun0 = -1e30f, mrun1 = -1e30f, lrun0 = 0.f, lrun1 = 0.f;

    const int r0 = q0 + w*16 + (lane >> 2);
    const int* mrow0 = mask + ((size_t)b_ * Ss + r0) * Ss;
    const int* mrow1 = mrow0 + 8 * (size_t)Ss;

    for (int it = 0; it < Ss / 64; it++) {
        const int kv0 = it * 64;
        #pragma unroll
        for (int i = tid; i < 64 * 16; i += 128) {
            int r = i >> 4, c4 = (i & 15) << 2;
            float4 t = *(const float4*)(Kp + (size_t)(kv0 + r) * Dd + c4);
            *(float4*)&Ksm[r * FLD + c4] =
                make_float4(to_tf32(t.x), to_tf32(t.y), to_tf32(t.z), to_tf32(t.w));
        }
        #pragma unroll
        for (int i = tid; i < 64 * 16; i += 128) {
            int r = i >> 4, c4 = (i & 15) << 2;
            float4 t = *(const float4*)(Vp + (size_t)r * Ss + kv0 + c4);
            *(float4*)&Vsm[r * FLD + c4] =
                make_float4(to_tf32(t.x), to_tf32(t.y), to_tf32(t.z), to_tf32(t.w));
        }
        __syncthreads();

        float sacc[8][4];
        #pragma unroll
        for (int i = 0; i < 8; i++)
            #pragma unroll
            for (int j = 0; j < 4; j++) sacc[i][j] = 0.f;
        #pragma unroll
        for (int ks = 0; ks < 8; ks++) {
            uint32_t bf[8][2];
            #pragma unroll
            for (int pq = 0; pq < 4; pq++) {
                const float* p = &Ksm[(pq*16 + ((mi >> 1) & 1)*8 + rr) * FLD + ks*8 + (mi & 1)*4];
                ldsm4(bf[2*pq][0], bf[2*pq][1], bf[2*pq+1][0], bf[2*pq+1][1], p);
            }
            #pragma unroll
            for (int nt = 0; nt < 8; nt++) mma_tf32(sacc[nt], qa[ks], bf[nt]);
        }

        float ml0 = -1e30f, ml1 = -1e30f;
        #pragma unroll
        for (int nt = 0; nt < 8; nt++) {
            int c = kv0 + nt*8 + (lane & 3)*2;
            int2 ma = *(const int2*)(mrow0 + c);
            int2 mb = *(const int2*)(mrow1 + c);
            sacc[nt][0] = ma.x ? sacc[nt][0] * SCALE : -1e30f;
            sacc[nt][1] = ma.y ? sacc[nt][1] * SCALE : -1e30f;
            sacc[nt][2] = mb.x ? sacc[nt][2] * SCALE : -1e30f;
            sacc[nt][3] = mb.y ? sacc[nt][3] * SCALE : -1e30f;
            ml0 = fmaxf(ml0, fmaxf(sacc[nt][0], sacc[nt][1]));
            ml1 = fmaxf(ml1, fmaxf(sacc[nt][2], sacc[nt][3]));
        }
        ml0 = fmaxf(ml0, __shfl_xor_sync(0xFFFFFFFFu, ml0, 1));
        ml0 = fmaxf(ml0, __shfl_xor_sync(0xFFFFFFFFu, ml0, 2));
        ml1 = fmaxf(ml1, __shfl_xor_sync(0xFFFFFFFFu, ml1, 1));
        ml1 = fmaxf(ml1, __shfl_xor_sync(0xFFFFFFFFu, ml1, 2));
        float mn0 = fmaxf(mrun0, ml0), mn1 = fmaxf(mrun1, ml1);
        float f0 = __expf(mrun0 - mn0), f1 = __expf(mrun1 - mn1);
        float ps0 = 0.f, ps1 = 0.f;
        #pragma unroll
        for (int nt = 0; nt < 8; nt++) {
            sacc[nt][0] = __expf(sacc[nt][0] - mn0);
            sacc[nt][1] = __expf(sacc[nt][1] - mn0);
            sacc[nt][2] = __expf(sacc[nt][2] - mn1);
            sacc[nt][3] = __expf(sacc[nt][3] - mn1);
            ps0 += sacc[nt][0] + sacc[nt][1];
            ps1 += sacc[nt][2] + sacc[nt][3];
        }
        ps0 += __shfl_xor_sync(0xFFFFFFFFu, ps0, 1);
        ps0 += __shfl_xor_sync(0xFFFFFFFFu, ps0, 2);
        ps1 += __shfl_xor_sync(0xFFFFFFFFu, ps1, 1);
        ps1 += __shfl_xor_sync(0xFFFFFFFFu, ps1, 2);
        lrun0 = lrun0 * f0 + ps0; lrun1 = lrun1 * f1 + ps1;
        mrun0 = mn0; mrun1 = mn1;
        #pragma unroll
        for (int nt = 0; nt < 8; nt++) {
            oacc[nt][0] *= f0; oacc[nt][1] *= f0;
            oacc[nt][2] *= f1; oacc[nt][3] *= f1;
        }
        {
            int pr = w*16 + (lane >> 2);
            #pragma unroll
            for (int nt = 0; nt < 8; nt++) {
                int c = nt*8 + (lane & 3)*2;
                *(float2*)&Psm[pr * FLD + c] =
                    make_float2(to_tf32(sacc[nt][0]), to_tf32(sacc[nt][1]));
                *(float2*)&Psm[(pr + 8) * FLD + c] =
                    make_float2(to_tf32(sacc[nt][2]), to_tf32(sacc[nt][3]));
            }
        }
        __syncthreads();

        #pragma unroll
        for (int ks = 0; ks < 8; ks++) {
            uint32_t pa[4];
            {
                const float* p = &Psm[(w*16 + (mi & 1)*8 + rr) * FLD + ks*8 + ((mi >> 1) & 1)*4];
                ldsm4(pa[0], pa[1], pa[2], pa[3], p);
            }
            uint32_t bf[8][2];
            #pragma unroll
            for (int pq = 0; pq < 4; pq++) {
                const float* p = &Vsm[(pq*16 + ((mi >> 1) & 1)*8 + rr) * FLD + ks*8 + (mi & 1)*4];
                ldsm4(bf[2*pq][0], bf[2*pq][1], bf[2*pq+1][0], bf[2*pq+1][1], p);
            }
            #pragma unroll
            for (int nt = 0; nt < 8; nt++) mma_tf32(oacc[nt], pa, bf[nt]);
        }
        __syncthreads();
    }

    float inv0 = 1.f / lrun0, inv1 = 1.f / lrun1;
    float* op = vals + ((size_t)b_ * Ss + r0) * Ee + h_ * Dd;
    #pragma unroll
    for (int nt = 0; nt < 8; nt++) {
        int c = nt*8 + (lane & 3)*2;
        *(float2*)(op + c) = make_float2(oacc[nt][0] * inv0, oacc[nt][1] * inv0);
        *(float2*)(op + (size_t)8 * Ee + c) = make_float2(oacc[nt][2] * inv1, oacc[nt][3] * inv1);
    }
}

// ---------------- tf32 dense GEMM: R7 structure, BK=32 ----------------
// C[m,n] = sum_k A[m,k] * B[n,k]; B is [N,K] row-major; 512 threads, 128x128 tile.
// EPI: 1=bias+relu, 2=bias+residual, 6=bias+QKV scatter (N=3072)
constexpr int GBM = 128, GBK = 32, GLD = 36;        // row stride 36: conflict-free ldmatrix
constexpr int TILE_F = GBM * GLD;                   // 4608 floats per (matrix, buffer)
constexpr int GEMM_SMEM = 4 * TILE_F * 4;           // 73728 bytes

template<int EPI>
__global__ void __launch_bounds__(512, 1)
gemm_tf32(const float* __restrict__ A, const float* __restrict__ Bm,
          const float* __restrict__ bias, const float* __restrict__ Res,
          float* __restrict__ C, int M, int N, int K)
{
    extern __shared__ float sms[];
    // layout: As[2][128][36] then Bs[2][128][36]
    float* Asm = sms;
    float* Bsm = sms + 2 * TILE_F;

    const int tid = threadIdx.x, lane = tid & 31, warp = tid >> 5;
    const int wm = warp >> 2, wn = warp & 3;
    const int rowBase = blockIdx.y * GBM, colBase = blockIdx.x * GBM;

    float acc[2][4][4];
    #pragma unroll
    for (int i = 0; i < 2; i++)
        #pragma unroll
        for (int j = 0; j < 4; j++)
            #pragma unroll
            for (int l = 0; l < 4; l++) acc[i][j][l] = 0.f;

    const int ntk = K / GBK;
    float4 ra[2], rb[2];
    // loader geometry: 1024 float4 slots per tile, 2 per thread
    const int l_r0 = (tid) >> 3,        l_c0 = ((tid) & 7) << 2;
    const int l_r1 = (tid + 512) >> 3,  l_c1 = ((tid + 512) & 7) << 2;

    ra[0] = *(const float4*)(A + (size_t)(rowBase + l_r0) * K + l_c0);
    ra[1] = *(const float4*)(A + (size_t)(rowBase + l_r1) * K + l_c1);
    rb[0] = *(const float4*)(Bm + (size_t)(colBase + l_r0) * K + l_c0);
    rb[1] = *(const float4*)(Bm + (size_t)(colBase + l_r1) * K + l_c1);
    {
        float4 v = ra[0];
        *(float4*)&Asm[l_r0 * GLD + l_c0] = make_float4(to_tf32(v.x), to_tf32(v.y), to_tf32(v.z), to_tf32(v.w));
        v = ra[1];
        *(float4*)&Asm[l_r1 * GLD + l_c1] = make_float4(to_tf32(v.x), to_tf32(v.y), to_tf32(v.z), to_tf32(v.w));
        v = rb[0];
        *(float4*)&Bsm[l_r0 * GLD + l_c0] = make_float4(to_tf32(v.x), to_tf32(v.y), to_tf32(v.z), to_tf32(v.w));
        v = rb[1];
        *(float4*)&Bsm[l_r1 * GLD + l_c1] = make_float4(to_tf32(v.x), to_tf32(v.y), to_tf32(v.z), to_tf32(v.w));
    }
    __syncthreads();

    const int mi = lane >> 3, rr = lane & 7;

    for (int kt = 0; kt < ntk; kt++) {
        const int buf = kt & 1;
        const float* Asb = Asm + buf * TILE_F;
        const float* Bsb = Bsm + buf * TILE_F;
        if (kt + 1 < ntk) {
            const int k0 = (kt + 1) * GBK;
            ra[0] = *(const float4*)(A + (size_t)(rowBase + l_r0) * K + k0 + l_c0);
            ra[1] = *(const float4*)(A + (size_t)(rowBase + l_r1) * K + k0 + l_c1);
            rb[0] = *(const float4*)(Bm + (size_t)(colBase + l_r0) * K + k0 + l_c0);
            rb[1] = *(const float4*)(Bm + (size_t)(colBase + l_r1) * K + k0 + l_c1);
        }
        #pragma unroll
        for (int ks = 0; ks < 4; ks++) {
            const int ko = ks * 8;
            uint32_t a[2][4], b[4][2];
            #pragma unroll
            for (int mt = 0; mt < 2; mt++) {
                const float* p = &Asb[(wm*32 + mt*16 + (mi & 1)*8 + rr) * GLD + ko + ((mi >> 1) & 1)*4];
                ldsm4(a[mt][0], a[mt][1], a[mt][2], a[mt][3], p);
            }
            #pragma unroll
            for (int pq = 0; pq < 2; pq++) {
                const float* p = &Bsb[(wn*32 + pq*16 + ((mi >> 1) & 1)*8 + rr) * GLD + ko + (mi & 1)*4];
                ldsm4(b[2*pq][0], b[2*pq][1], b[2*pq+1][0], b[2*pq+1][1], p);
            }
            #pragma unroll
            for (int mt = 0; mt < 2; mt++)
                #pragma unroll
                for (int nt = 0; nt < 4; nt++)
                    mma_tf32(acc[mt][nt], a[mt], b[nt]);
        }
        if (kt + 1 < ntk) {
            float* Asn = Asm + (buf ^ 1) * TILE_F;
            float* Bsn = Bsm + (buf ^ 1) * TILE_F;
            float4 v = ra[0];
            *(float4*)&Asn[l_r0 * GLD + l_c0] = make_float4(to_tf32(v.x), to_tf32(v.y), to_tf32(v.z), to_tf32(v.w));
            v = ra[1];
            *(float4*)&Asn[l_r1 * GLD + l_c1] = make_float4(to_tf32(v.x), to_tf32(v.y), to_tf32(v.z), to_tf32(v.w));
            v = rb[0];
            *(float4*)&Bsn[l_r0 * GLD + l_c0] = make_float4(to_tf32(v.x), to_tf32(v.y), to_tf32(v.z), to_tf32(v.w));
            v = rb[1];
            *(float4*)&Bsn[l_r1 * GLD + l_c1] = make_float4(to_tf32(v.x), to_tf32(v.y), to_tf32(v.z), to_tf32(v.w));
        }
        __syncthreads();
    }

    // ---- epilogue ----
    #pragma unroll
    for (int mt = 0; mt < 2; mt++)
        #pragma unroll
        for (int half = 0; half < 2; half++) {
            const int row = rowBase + wm*32 + mt*16 + (lane >> 2) + half*8;
            #pragma unroll
            for (int nt = 0; nt < 4; nt++) {
                const int col = colBase + wn*32 + nt*8 + (lane & 3)*2;
                float v0 = acc[mt][nt][half*2 + 0];
                float v1 = acc[mt][nt][half*2 + 1];
                float2 bb = *(const float2*)(bias + col);
                v0 += bb.x; v1 += bb.y;
                if constexpr (EPI == 1) {
                    *(float2*)(C + (size_t)row * N + col) =
                        make_float2(fmaxf(v0, 0.f), fmaxf(v1, 0.f));
                } else if constexpr (EPI == 2) {
                    float2 r2 = *(const float2*)(Res + (size_t)row * N + col);
                    *(float2*)(C + (size_t)row * N + col) = make_float2(v0 + r2.x, v1 + r2.y);
                } else { // EPI == 6: QKV scatter (fp32, matches R7 numerics)
                    int b_ = row / Ss, s_ = row - b_ * Ss;
                    if (col < Ee) {
                        int h_ = col >> 6, d_ = col & 63;
                        *(float2*)(g_q + (((size_t)b_ * Hh + h_) * Ss + s_) * Dd + d_) = make_float2(v0, v1);
                    } else if (col < 2 * Ee) {
                        int c2 = col - Ee, h_ = c2 >> 6, d_ = c2 & 63;
                        *(float2*)(g_k + (((size_t)b_ * Hh + h_) * Ss + s_) * Dd + d_) = make_float2(v0, v1);
                    } else {
                        int c2 = col - 2 * Ee, h_ = c2 >> 6, d_ = c2 & 63;
                        float* pp = g_v + (((size_t)b_ * Hh + h_) * Dd + d_) * Ss + s_;
                        pp[0]  = v0;
                        pp[Ss] = v1;
                    }
                }
            }
        }
}

// ---------------- orchestration ----------------
extern "C" void kernel_launch(void* const* d_in, const int* in_sizes, int n_in,
                              void* d_out, int out_size)
{
    const float* x    = (const float*)d_in[0];
    const int*   mask = (const int*)  d_in[1];
    const float* wq   = (const float*)d_in[2];
    const float* bq   = (const float*)d_in[3];
    const float* wk   = (const float*)d_in[4];
    const float* bk   = (const float*)d_in[5];
    const float* wv   = (const float*)d_in[6];
    const float* bv   = (const float*)d_in[7];
    const float* wo   = (const float*)d_in[8];
    const float* bo   = (const float*)d_in[9];
    const float* w1   = (const float*)d_in[10];
    const float* b1   = (const float*)d_in[11];
    const float* w2   = (const float*)d_in[12];
    const float* b2   = (const float*)d_in[13];
    const float* ln1w = (const float*)d_in[14];
    const float* ln1b = (const float*)d_in[15];
    const float* ln2w = (const float*)d_in[16];
    const float* ln2b = (const float*)d_in[17];
    float* out = (float*)d_out;

    float *nx, *q, *k, *v, *vals, *x1, *hbuf, *wqkv, *bqkv;
    cudaGetSymbolAddress((void**)&nx,   g_nx);
    cudaGetSymbolAddress((void**)&q,    g_q);
    cudaGetSymbolAddress((void**)&k,    g_k);
    cudaGetSymbolAddress((void**)&v,    g_v);
    cudaGetSymbolAddress((void**)&vals, g_vals);
    cudaGetSymbolAddress((void**)&x1,   g_x1);
    cudaGetSymbolAddress((void**)&hbuf, g_h);
    cudaGetSymbolAddress((void**)&wqkv, g_wqkv);
    cudaGetSymbolAddress((void**)&bqkv, g_bqkv);

    const int flash_smem = 3 * 64 * FLD * sizeof(float);
    cudaFuncSetAttribute(flash_kernel, cudaFuncAttributeMaxDynamicSharedMemorySize, flash_smem);
    cudaFuncSetAttribute(gemm_tf32<1>, cudaFuncAttributeMaxDynamicSharedMemorySize, GEMM_SMEM);
    cudaFuncSetAttribute(gemm_tf32<2>, cudaFuncAttributeMaxDynamicSharedMemorySize, GEMM_SMEM);
    cudaFuncSetAttribute(gemm_tf32<6>, cudaFuncAttributeMaxDynamicSharedMemorySize, GEMM_SMEM);

    // 0. pack QKV weights/biases (raw copy, ~6us)
    pack_qkv_w<<<3 * Ee, 256>>>(wq, wk, wv, wqkv);
    pack_qkv_b<<<3, Ee>>>(bq, bk, bv, bqkv);

    // 1. LN1
    ln_kernel<<<Mtok, 256>>>(x, ln1w, ln1b, nx);

    // 2. fused QKV projection -> q, k, v(transposed)
    {
        dim3 g(3 * Ee / 128, Mtok / 128);
        gemm_tf32<6><<<g, 512, GEMM_SMEM>>>(nx, wqkv, bqkv, nullptr, nullptr, Mtok, 3 * Ee, Ee);
    }

    // 3. flash attention -> vals
    {
        dim3 g(Ss / 64, Bb * Hh);
        flash_kernel<<<g, 128, flash_smem>>>(q, k, v, mask, vals);
    }

    // 4. O projection + residual -> x1
    {
        dim3 g(Ee / 128, Mtok / 128);
        gemm_tf32<2><<<g, 512, GEMM_SMEM>>>(vals, wo, bo, x, x1, Mtok, Ee, Ee);
    }

    // 5. LN2
    ln_kernel<<<Mtok, 256>>>(x1, ln2w, ln2b, nx);

    // 6. FFN1 (relu) -> hbuf
    {
        dim3 g(Ff / 128, Mtok / 128);
        gemm_tf32<1><<<g, 512, GEMM_SMEM>>>(nx, w1, b1, nullptr, hbuf, Mtok, Ff, Ee);
    }

    // 7. FFN2 + residual -> out
    {
        dim3 g(Ee / 128, Mtok / 128);
        gemm_tf32<2><<<g, 512, GEMM_SMEM>>>(hbuf, w2, b2, x1, out, Mtok, Ee, Ff);
    }
}

// round 13
// speedup vs baseline: 1.6357x; 1.0414x over previous
#include <cuda_runtime.h>
#include <math.h>
#include <stdint.h>

// ---------------- problem constants ----------------
constexpr int   Bb   = 2;
constexpr int   Ss   = 2048;
constexpr int   Ee   = 1024;
constexpr int   Hh   = 16;
constexpr int   Dd   = 64;
constexpr int   Ff   = 4096;
constexpr int   Mtok = Bb * Ss;
constexpr float EPSc  = 1e-5f;
constexpr float SCALE = 0.125f;

// ---------------- scratch ----------------
__device__ float g_nx  [(size_t)Mtok * Ee];
__device__ float g_q   [(size_t)Mtok * Ee];   // [B,H,S,D]
__device__ float g_k   [(size_t)Mtok * Ee];   // [B,H,S,D]
__device__ float g_v   [(size_t)Mtok * Ee];   // [B,H,D,S]  (transposed)
__device__ float g_vals[(size_t)Mtok * Ee];   // [B,S,E]
__device__ float g_x1  [(size_t)Mtok * Ee];
__device__ float g_h   [(size_t)Mtok * Ff];
__device__ float g_wqkv[(size_t)3 * Ee * Ee]; // packed [3072,1024] (raw copy)
__device__ float g_bqkv[3 * Ee];

// ---------------- tf32 helpers ----------------
__device__ __forceinline__ float to_tf32(float x) {
    float r; asm("cvt.rna.tf32.f32 %0, %1;" : "=f"(r) : "f"(x)); return r;
}
__device__ __forceinline__ void ldsm4(uint32_t& r0, uint32_t& r1, uint32_t& r2, uint32_t& r3,
                                      const float* p) {
    uint32_t a = (uint32_t)__cvta_generic_to_shared(p);
    asm volatile("ldmatrix.sync.aligned.m8n8.x4.shared.b16 {%0,%1,%2,%3}, [%4];"
                 : "=r"(r0), "=r"(r1), "=r"(r2), "=r"(r3) : "r"(a));
}
__device__ __forceinline__ void mma_tf32(float* c, const uint32_t* a, const uint32_t* b) {
    asm volatile("mma.sync.aligned.m16n8k8.row.col.f32.tf32.tf32.f32 "
                 "{%0,%1,%2,%3}, {%4,%5,%6,%7}, {%8,%9}, {%0,%1,%2,%3};"
                 : "+f"(c[0]), "+f"(c[1]), "+f"(c[2]), "+f"(c[3])
                 : "r"(a[0]), "r"(a[1]), "r"(a[2]), "r"(a[3]), "r"(b[0]), "r"(b[1]));
}

// ---------------- pack kernels (raw copies, no rounding) ----------------
__global__ void pack_qkv_w(const float* __restrict__ wq, const float* __restrict__ wk,
                           const float* __restrict__ wv, float* __restrict__ dst)
{
    const int row = blockIdx.x;  // 0..3071
    const float* src = (row < Ee)     ? wq + (size_t)row * Ee
                     : (row < 2 * Ee) ? wk + (size_t)(row - Ee) * Ee
                                      : wv + (size_t)(row - 2 * Ee) * Ee;
    ((float4*)(dst + (size_t)row * Ee))[threadIdx.x] = ((const float4*)src)[threadIdx.x];
}
__global__ void pack_qkv_b(const float* __restrict__ bq, const float* __restrict__ bk,
                           const float* __restrict__ bv, float* __restrict__ dst)
{
    const float* s = blockIdx.x == 0 ? bq : blockIdx.x == 1 ? bk : bv;
    dst[blockIdx.x * Ee + threadIdx.x] = s[threadIdx.x];
}

// ---------------- reductions ----------------
__device__ __forceinline__ float warpSum(float v) {
    #pragma unroll
    for (int o = 16; o; o >>= 1) v += __shfl_xor_sync(0xFFFFFFFFu, v, o);
    return v;
}
__device__ __forceinline__ float blockSum(float v, float* sh, float* bc) {
    int lane = threadIdx.x & 31, wid = threadIdx.x >> 5;
    v = warpSum(v);
    if (!lane) sh[wid] = v;
    __syncthreads();
    if (wid == 0) {
        v = (lane < 8) ? sh[lane] : 0.f;
        v = warpSum(v);
        if (!lane) *bc = v;
    }
    __syncthreads();
    return *bc;
}

// ---------------- LayerNorm ----------------
__global__ void ln_kernel(const float* __restrict__ x, const float* __restrict__ w,
                          const float* __restrict__ b, float* __restrict__ out)
{
    __shared__ float sh[32];
    __shared__ float bc;
    const int row = blockIdx.x, t = threadIdx.x;
    float4 v = *(const float4*)(x + (size_t)row * Ee + t * 4);
    float mean = blockSum(v.x + v.y + v.z + v.w, sh, &bc) * (1.f / Ee);
    float dx0 = v.x - mean, dx1 = v.y - mean, dx2 = v.z - mean, dx3 = v.w - mean;
    float var = blockSum(dx0*dx0 + dx1*dx1 + dx2*dx2 + dx3*dx3, sh, &bc) * (1.f / (Ee - 1));
    float r = 1.f / (sqrtf(var) + EPSc);
    float4 wv = *(const float4*)(w + t * 4);
    float4 bv = *(const float4*)(b + t * 4);
    float4 o;
    o.x = wv.x * dx0 * r + bv.x;
    o.y = wv.y * dx1 * r + bv.y;
    o.z = wv.z * dx2 * r + bv.z;
    o.w = wv.w * dx3 * r + bv.w;
    *(float4*)(out + (size_t)row * Ee + t * 4) = o;
}

// ---------------- flash attention: Br=64, Bc=64, 4 warps (R7 verbatim) ----------------
constexpr int FLD = 68;

__global__ void __launch_bounds__(128)
flash_kernel(const float* __restrict__ q, const float* __restrict__ k,
             const float* __restrict__ v, const int* __restrict__ mask,
             float* __restrict__ vals)
{
    extern __shared__ float sm[];
    float* Ksm = sm;
    float* Vsm = Ksm + 64 * FLD;
    float* Psm = Vsm + 64 * FLD;

    const int bh = blockIdx.y;
    const int b_ = bh >> 4, h_ = bh & 15;
    const int q0 = blockIdx.x * 64;
    const int tid = threadIdx.x, lane = tid & 31, w = tid >> 5;
    const int mi = lane >> 3, rr = lane & 7;

    const float* Qp = q + ((size_t)bh * Ss + q0) * Dd;
    const float* Kp = k + (size_t)bh * Ss * Dd;
    const float* Vp = v + (size_t)bh * Dd * Ss;

    #pragma unroll
    for (int i = tid; i < 64 * 16; i += 128) {
        int r = i >> 4, c4 = (i & 15) << 2;
        float4 t = *(const float4*)(Qp + (size_t)r * Dd + c4);
        *(float4*)&Psm[r * FLD + c4] =
            make_float4(to_tf32(t.x), to_tf32(t.y), to_tf32(t.z), to_tf32(t.w));
    }
    __syncthreads();
    uint32_t qa[8][4];
    #pragma unroll
    for (int ks = 0; ks < 8; ks++) {
        const float* p = &Psm[(w*16 + (mi & 1)*8 + rr) * FLD + ks*8 + ((mi >> 1) & 1)*4];
        ldsm4(qa[ks][0], qa[ks][1], qa[ks][2], qa[ks][3], p);
    }

    float oacc[8][4];
    #pragma unroll
    for (int i = 0; i < 8; i++)
        #pragma unroll
        for (int j = 0; j < 4; j++) oacc[i][j] = 0.f;
    float mrun0 = -1e30f, mrun1 = -1e30f, lrun0 = 0.f, lrun1 = 0.f;

    const int r0 = q0 + w*16 + (lane >> 2);
    const int* mrow0 = mask + ((size_t)b_ * Ss + r0) * Ss;
    const int* mrow1 = mrow0 + 8 * (size_t)Ss;

    for (int it = 0; it < Ss / 64; it++) {
        const int kv0 = it * 64;
        #pragma unroll
        for (int i = tid; i < 64 * 16; i += 128) {
            int r = i >> 4, c4 = (i & 15) << 2;
            float4 t = *(const float4*)(Kp + (size_t)(kv0 + r) * Dd + c4);
            *(float4*)&Ksm[r * FLD + c4] =
                make_float4(to_tf32(t.x), to_tf32(t.y), to_tf32(t.z), to_tf32(t.w));
        }
        #pragma unroll
        for (int i = tid; i < 64 * 16; i += 128) {
            int r = i >> 4, c4 = (i & 15) << 2;
            float4 t = *(const float4*)(Vp + (size_t)r * Ss + kv0 + c4);
            *(float4*)&Vsm[r * FLD + c4] =
                make_float4(to_tf32(t.x), to_tf32(t.y), to_tf32(t.z), to_tf32(t.w));
        }
        __syncthreads();

        float sacc[8][4];
        #pragma unroll
        for (int i = 0; i < 8; i++)
            #pragma unroll
            for (int j = 0; j < 4; j++) sacc[i][j] = 0.f;
        #pragma unroll
        for (int ks = 0; ks < 8; ks++) {
            uint32_t bf[8][2];
            #pragma unroll
            for (int pq = 0; pq < 4; pq++) {
                const float* p = &Ksm[(pq*16 + ((mi >> 1) & 1)*8 + rr) * FLD + ks*8 + (mi & 1)*4];
                ldsm4(bf[2*pq][0], bf[2*pq][1], bf[2*pq+1][0], bf[2*pq+1][1], p);
            }
            #pragma unroll
            for (int nt = 0; nt < 8; nt++) mma_tf32(sacc[nt], qa[ks], bf[nt]);
        }

        float ml0 = -1e30f, ml1 = -1e30f;
        #pragma unroll
        for (int nt = 0; nt < 8; nt++) {
            int c = kv0 + nt*8 + (lane & 3)*2;
            int2 ma = *(const int2*)(mrow0 + c);
            int2 mb = *(const int2*)(mrow1 + c);
            sacc[nt][0] = ma.x ? sacc[nt][0] * SCALE : -1e30f;
            sacc[nt][1] = ma.y ? sacc[nt][1] * SCALE : -1e30f;
            sacc[nt][2] = mb.x ? sacc[nt][2] * SCALE : -1e30f;
            sacc[nt][3] = mb.y ? sacc[nt][3] * SCALE : -1e30f;
            ml0 = fmaxf(ml0, fmaxf(sacc[nt][0], sacc[nt][1]));
            ml1 = fmaxf(ml1, fmaxf(sacc[nt][2], sacc[nt][3]));
        }
        ml0 = fmaxf(ml0, __shfl_xor_sync(0xFFFFFFFFu, ml0, 1));
        ml0 = fmaxf(ml0, __shfl_xor_sync(0xFFFFFFFFu, ml0, 2));
        ml1 = fmaxf(ml1, __shfl_xor_sync(0xFFFFFFFFu, ml1, 1));
        ml1 = fmaxf(ml1, __shfl_xor_sync(0xFFFFFFFFu, ml1, 2));
        float mn0 = fmaxf(mrun0, ml0), mn1 = fmaxf(mrun1, ml1);
        float f0 = __expf(mrun0 - mn0), f1 = __expf(mrun1 - mn1);
        float ps0 = 0.f, ps1 = 0.f;
        #pragma unroll
        for (int nt = 0; nt < 8; nt++) {
            sacc[nt][0] = __expf(sacc[nt][0] - mn0);
            sacc[nt][1] = __expf(sacc[nt][1] - mn0);
            sacc[nt][2] = __expf(sacc[nt][2] - mn1);
            sacc[nt][3] = __expf(sacc[nt][3] - mn1);
            ps0 += sacc[nt][0] + sacc[nt][1];
            ps1 += sacc[nt][2] + sacc[nt][3];
        }
        ps0 += __shfl_xor_sync(0xFFFFFFFFu, ps0, 1);
        ps0 += __shfl_xor_sync(0xFFFFFFFFu, ps0, 2);
        ps1 += __shfl_xor_sync(0xFFFFFFFFu, ps1, 1);
        ps1 += __shfl_xor_sync(0xFFFFFFFFu, ps1, 2);
        lrun0 = lrun0 * f0 + ps0; lrun1 = lrun1 * f1 + ps1;
        mrun0 = mn0; mrun1 = mn1;
        #pragma unroll
        for (int nt = 0; nt < 8; nt++) {
            oacc[nt][0] *= f0; oacc[nt][1] *= f0;
            oacc[nt][2] *= f1; oacc[nt][3] *= f1;
        }
        {
            int pr = w*16 + (lane >> 2);
            #pragma unroll
            for (int nt = 0; nt < 8; nt++) {
                int c = nt*8 + (lane & 3)*2;
                *(float2*)&Psm[pr * FLD + c] =
                    make_float2(to_tf32(sacc[nt][0]), to_tf32(sacc[nt][1]));
                *(float2*)&Psm[(pr + 8) * FLD + c] =
                    make_float2(to_tf32(sacc[nt][2]), to_tf32(sacc[nt][3]));
            }
        }
        __syncthreads();

        #pragma unroll
        for (int ks = 0; ks < 8; ks++) {
            uint32_t pa[4];
            {
                const float* p = &Psm[(w*16 + (mi & 1)*8 + rr) * FLD + ks*8 + ((mi >> 1) & 1)*4];
                ldsm4(pa[0], pa[1], pa[2], pa[3], p);
            }
            uint32_t bf[8][2];
            #pragma unroll
            for (int pq = 0; pq < 4; pq++) {
                const float* p = &Vsm[(pq*16 + ((mi >> 1) & 1)*8 + rr) * FLD + ks*8 + (mi & 1)*4];
                ldsm4(bf[2*pq][0], bf[2*pq][1], bf[2*pq+1][0], bf[2*pq+1][1], p);
            }
            #pragma unroll
            for (int nt = 0; nt < 8; nt++) mma_tf32(oacc[nt], pa, bf[nt]);
        }
        __syncthreads();
    }

    float inv0 = 1.f / lrun0, inv1 = 1.f / lrun1;
    float* op = vals + ((size_t)b_ * Ss + r0) * Ee + h_ * Dd;
    #pragma unroll
    for (int nt = 0; nt < 8; nt++) {
        int c = nt*8 + (lane & 3)*2;
        *(float2*)(op + c) = make_float2(oacc[nt][0] * inv0, oacc[nt][1] * inv0);
        *(float2*)(op + (size_t)8 * Ee + c) = make_float2(oacc[nt][2] * inv1, oacc[nt][3] * inv1);
    }
}

// ---------------- tf32 dense GEMM: BK=32, 8 warps, warp tile 32x64, 2 CTAs/SM ----------------
// C[m,n] = sum_k A[m,k] * B[n,k]; B is [N,K] row-major; 256 threads, 128x128 tile.
// EPI: 1=bias+relu, 2=bias+residual, 6=bias+QKV scatter (N=3072)
constexpr int GBM = 128, GBK = 32, GLD = 36;
constexpr int TILE_F = GBM * GLD;                   // 4608 floats per (matrix, buffer)
constexpr int GEMM_SMEM = 4 * TILE_F * 4;           // 73728 bytes

template<int EPI>
__global__ void __launch_bounds__(256, 2)
gemm_tf32(const float* __restrict__ A, const float* __restrict__ Bm,
          const float* __restrict__ bias, const float* __restrict__ Res,
          float* __restrict__ C, int M, int N, int K)
{
    extern __shared__ float sms[];
    float* Asm = sms;
    float* Bsm = sms + 2 * TILE_F;

    const int tid = threadIdx.x, lane = tid & 31, warp = tid >> 5;
    const int wm = warp >> 1, wn = warp & 1;          // 4(m) x 2(n) warps; warp tile 32x64
    const int rowBase = blockIdx.y * GBM, colBase = blockIdx.x * GBM;

    float acc[2][8][4];
    #pragma unroll
    for (int i = 0; i < 2; i++)
        #pragma unroll
        for (int j = 0; j < 8; j++)
            #pragma unroll
            for (int l = 0; l < 4; l++) acc[i][j][l] = 0.f;

    const int ntk = K / GBK;
    float4 ra[4], rb[4];
    // loader: 1024 float4 slots per tile, 4 per thread
    const int l_r[4] = { tid >> 3, (tid + 256) >> 3, (tid + 512) >> 3, (tid + 768) >> 3 };
    const int l_c = (tid & 7) << 2;

    #pragma unroll
    for (int i = 0; i < 4; i++) {
        ra[i] = *(const float4*)(A + (size_t)(rowBase + l_r[i]) * K + l_c);
        rb[i] = *(const float4*)(Bm + (size_t)(colBase + l_r[i]) * K + l_c);
    }
    #pragma unroll
    for (int i = 0; i < 4; i++) {
        float4 v = ra[i];
        *(float4*)&Asm[l_r[i] * GLD + l_c] = make_float4(to_tf32(v.x), to_tf32(v.y), to_tf32(v.z), to_tf32(v.w));
        v = rb[i];
        *(float4*)&Bsm[l_r[i] * GLD + l_c] = make_float4(to_tf32(v.x), to_tf32(v.y), to_tf32(v.z), to_tf32(v.w));
    }
    __syncthreads();

    const int mi = lane >> 3, rr = lane & 7;

    for (int kt = 0; kt < ntk; kt++) {
        const int buf = kt & 1;
        const float* Asb = Asm + buf * TILE_F;
        const float* Bsb = Bsm + buf * TILE_F;
        if (kt + 1 < ntk) {
            const int k0 = (kt + 1) * GBK;
            #pragma unroll
            for (int i = 0; i < 4; i++) {
                ra[i] = *(const float4*)(A + (size_t)(rowBase + l_r[i]) * K + k0 + l_c);
                rb[i] = *(const float4*)(Bm + (size_t)(colBase + l_r[i]) * K + k0 + l_c);
            }
        }
        #pragma unroll
        for (int ks = 0; ks < 4; ks++) {
            const int ko = ks * 8;
            uint32_t a[2][4], b[8][2];
            #pragma unroll
            for (int mt = 0; mt < 2; mt++) {
                const float* p = &Asb[(wm*32 + mt*16 + (mi & 1)*8 + rr) * GLD + ko + ((mi >> 1) & 1)*4];
                ldsm4(a[mt][0], a[mt][1], a[mt][2], a[mt][3], p);
            }
            #pragma unroll
            for (int pq = 0; pq < 4; pq++) {
                const float* p = &Bsb[(wn*64 + pq*16 + ((mi >> 1) & 1)*8 + rr) * GLD + ko + (mi & 1)*4];
                ldsm4(b[2*pq][0], b[2*pq][1], b[2*pq+1][0], b[2*pq+1][1], p);
            }
            #pragma unroll
            for (int mt = 0; mt < 2; mt++)
                #pragma unroll
                for (int nt = 0; nt < 8; nt++)
                    mma_tf32(acc[mt][nt], a[mt], b[nt]);
        }
        if (kt + 1 < ntk) {
            float* Asn = Asm + (buf ^ 1) * TILE_F;
            float* Bsn = Bsm + (buf ^ 1) * TILE_F;
            #pragma unroll
            for (int i = 0; i < 4; i++) {
                float4 v = ra[i];
                *(float4*)&Asn[l_r[i] * GLD + l_c] = make_float4(to_tf32(v.x), to_tf32(v.y), to_tf32(v.z), to_tf32(v.w));
                v = rb[i];
                *(float4*)&Bsn[l_r[i] * GLD + l_c] = make_float4(to_tf32(v.x), to_tf32(v.y), to_tf32(v.z), to_tf32(v.w));
            }
        }
        __syncthreads();
    }

    // ---- epilogue ----
    #pragma unroll
    for (int mt = 0; mt < 2; mt++)
        #pragma unroll
        for (int half = 0; half < 2; half++) {
            const int row = rowBase + wm*32 + mt*16 + (lane >> 2) + half*8;
            #pragma unroll
            for (int nt = 0; nt < 8; nt++) {
                const int col = colBase + wn*64 + nt*8 + (lane & 3)*2;
                float v0 = acc[mt][nt][half*2 + 0];
                float v1 = acc[mt][nt][half*2 + 1];
                float2 bb = *(const float2*)(bias + col);
                v0 += bb.x; v1 += bb.y;
                if constexpr (EPI == 1) {
                    *(float2*)(C + (size_t)row * N + col) =
                        make_float2(fmaxf(v0, 0.f), fmaxf(v1, 0.f));
                } else if constexpr (EPI == 2) {
                    float2 r2 = *(const float2*)(Res + (size_t)row * N + col);
                    *(float2*)(C + (size_t)row * N + col) = make_float2(v0 + r2.x, v1 + r2.y);
                } else { // EPI == 6: QKV scatter
                    int b_ = row / Ss, s_ = row - b_ * Ss;
                    if (col < Ee) {
                        int h_ = col >> 6, d_ = col & 63;
                        *(float2*)(g_q + (((size_t)b_ * Hh + h_) * Ss + s_) * Dd + d_) = make_float2(v0, v1);
                    } else if (col < 2 * Ee) {
                        int c2 = col - Ee, h_ = c2 >> 6, d_ = c2 & 63;
                        *(float2*)(g_k + (((size_t)b_ * Hh + h_) * Ss + s_) * Dd + d_) = make_float2(v0, v1);
                    } else {
                        int c2 = col - 2 * Ee, h_ = c2 >> 6, d_ = c2 & 63;
                        float* pp = g_v + (((size_t)b_ * Hh + h_) * Dd + d_) * Ss + s_;
                        pp[0]  = v0;
                        pp[Ss] = v1;
                    }
                }
            }
        }
}

// ---------------- orchestration ----------------
extern "C" void kernel_launch(void* const* d_in, const int* in_sizes, int n_in,
                              void* d_out, int out_size)
{
    const float* x    = (const float*)d_in[0];
    const int*   mask = (const int*)  d_in[1];
    const float* wq   = (const float*)d_in[2];
    const float* bq   = (const float*)d_in[3];
    const float* wk   = (const float*)d_in[4];
    const float* bk   = (const float*)d_in[5];
    const float* wv   = (const float*)d_in[6];
    const float* bv   = (const float*)d_in[7];
    const float* wo   = (const float*)d_in[8];
    const float* bo   = (const float*)d_in[9];
    const float* w1   = (const float*)d_in[10];
    const float* b1   = (const float*)d_in[11];
    const float* w2   = (const float*)d_in[12];
    const float* b2   = (const float*)d_in[13];
    const float* ln1w = (const float*)d_in[14];
    const float* ln1b = (const float*)d_in[15];
    const float* ln2w = (const float*)d_in[16];
    const float* ln2b = (const float*)d_in[17];
    float* out = (float*)d_out;

    float *nx, *q, *k, *v, *vals, *x1, *hbuf, *wqkv, *bqkv;
    cudaGetSymbolAddress((void**)&nx,   g_nx);
    cudaGetSymbolAddress((void**)&q,    g_q);
    cudaGetSymbolAddress((void**)&k,    g_k);
    cudaGetSymbolAddress((void**)&v,    g_v);
    cudaGetSymbolAddress((void**)&vals, g_vals);
    cudaGetSymbolAddress((void**)&x1,   g_x1);
    cudaGetSymbolAddress((void**)&hbuf, g_h);
    cudaGetSymbolAddress((void**)&wqkv, g_wqkv);
    cudaGetSymbolAddress((void**)&bqkv, g_bqkv);

    const int flash_smem = 3 * 64 * FLD * sizeof(float);
    cudaFuncSetAttribute(flash_kernel, cudaFuncAttributeMaxDynamicSharedMemorySize, flash_smem);
    cudaFuncSetAttribute(gemm_tf32<1>, cudaFuncAttributeMaxDynamicSharedMemorySize, GEMM_SMEM);
    cudaFuncSetAttribute(gemm_tf32<2>, cudaFuncAttributeMaxDynamicSharedMemorySize, GEMM_SMEM);
    cudaFuncSetAttribute(gemm_tf32<6>, cudaFuncAttributeMaxDynamicSharedMemorySize, GEMM_SMEM);

    // 0. pack QKV weights/biases (raw copy, ~6us)
    pack_qkv_w<<<3 * Ee, 256>>>(wq, wk, wv, wqkv);
    pack_qkv_b<<<3, Ee>>>(bq, bk, bv, bqkv);

    // 1. LN1
    ln_kernel<<<Mtok, 256>>>(x, ln1w, ln1b, nx);

    // 2. fused QKV projection -> q, k, v(transposed)
    {
        dim3 g(3 * Ee / 128, Mtok / 128);
        gemm_tf32<6><<<g, 256, GEMM_SMEM>>>(nx, wqkv, bqkv, nullptr, nullptr, Mtok, 3 * Ee, Ee);
    }

    // 3. flash attention -> vals
    {
        dim3 g(Ss / 64, Bb * Hh);
        flash_kernel<<<g, 128, flash_smem>>>(q, k, v, mask, vals);
    }

    // 4. O projection + residual -> x1
    {
        dim3 g(Ee / 128, Mtok / 128);
        gemm_tf32<2><<<g, 256, GEMM_SMEM>>>(vals, wo, bo, x, x1, Mtok, Ee, Ee);
    }

    // 5. LN2
    ln_kernel<<<Mtok, 256>>>(x1, ln2w, ln2b, nx);

    // 6. FFN1 (relu) -> hbuf
    {
        dim3 g(Ff / 128, Mtok / 128);
        gemm_tf32<1><<<g, 256, GEMM_SMEM>>>(nx, w1, b1, nullptr, hbuf, Mtok, Ff, Ee);
    }

    // 7. FFN2 + residual -> out
    {
        dim3 g(Ee / 128, Mtok / 128);
        gemm_tf32<2><<<g, 256, GEMM_SMEM>>>(hbuf, w2, b2, x1, out, Mtok, Ee, Ff);
    }
}

// round 16
// speedup vs baseline: 1.8810x; 1.1500x over previous
#include <cuda_runtime.h>
#include <math.h>
#include <stdint.h>

// ---------------- problem constants ----------------
constexpr int   Bb   = 2;
constexpr int   Ss   = 2048;
constexpr int   Ee   = 1024;
constexpr int   Hh   = 16;
constexpr int   Dd   = 64;
constexpr int   Ff   = 4096;
constexpr int   Mtok = Bb * Ss;
constexpr float EPSc  = 1e-5f;
constexpr float SCALE = 0.125f;

// ---------------- scratch ----------------
__device__ float g_nx  [(size_t)Mtok * Ee];   // tf32-rounded
__device__ float g_q   [(size_t)Mtok * Ee];   // [B,H,S,D] tf32-rounded
__device__ float g_k   [(size_t)Mtok * Ee];   // [B,H,S,D] tf32-rounded
__device__ float g_v   [(size_t)Mtok * Ee];   // [B,H,D,S] tf32-rounded (transposed)
__device__ float g_vals[(size_t)Mtok * Ee];   // [B,S,E]   tf32-rounded
__device__ float g_x1  [(size_t)Mtok * Ee];   // fp32
__device__ float g_h   [(size_t)Mtok * Ff];   // tf32-rounded (relu out)
__device__ float g_wqkv[(size_t)3 * Ee * Ee]; // packed + rounded
__device__ float g_bqkv[3 * Ee];
__device__ float g_wo  [(size_t)Ee * Ee];     // rounded copies
__device__ float g_w1  [(size_t)Ff * Ee];
__device__ float g_w2  [(size_t)Ee * Ff];

// ---------------- tf32 helpers ----------------
__device__ __forceinline__ float to_tf32(float x) {
    float r; asm("cvt.rna.tf32.f32 %0, %1;" : "=f"(r) : "f"(x)); return r;
}
__device__ __forceinline__ void ldsm4(uint32_t& r0, uint32_t& r1, uint32_t& r2, uint32_t& r3,
                                      const float* p) {
    uint32_t a = (uint32_t)__cvta_generic_to_shared(p);
    asm volatile("ldmatrix.sync.aligned.m8n8.x4.shared.b16 {%0,%1,%2,%3}, [%4];"
                 : "=r"(r0), "=r"(r1), "=r"(r2), "=r"(r3) : "r"(a));
}
__device__ __forceinline__ void mma_tf32(float* c, const uint32_t* a, const uint32_t* b) {
    asm volatile("mma.sync.aligned.m16n8k8.row.col.f32.tf32.tf32.f32 "
                 "{%0,%1,%2,%3}, {%4,%5,%6,%7}, {%8,%9}, {%0,%1,%2,%3};"
                 : "+f"(c[0]), "+f"(c[1]), "+f"(c[2]), "+f"(c[3])
                 : "r"(a[0]), "r"(a[1]), "r"(a[2]), "r"(a[3]), "r"(b[0]), "r"(b[1]));
}
__device__ __forceinline__ void cp16(float* smem_dst, const float* gmem_src) {
    uint32_t a = (uint32_t)__cvta_generic_to_shared(smem_dst);
    asm volatile("cp.async.cg.shared.global [%0], [%1], 16;" :: "r"(a), "l"(gmem_src));
}
__device__ __forceinline__ void cp_commit() { asm volatile("cp.async.commit_group;"); }
template<int N> __device__ __forceinline__ void cp_wait() {
    asm volatile("cp.async.wait_group %0;" :: "n"(N));
}

// ---------------- pack / round kernels ----------------
__global__ void pack_qkv_w(const float* __restrict__ wq, const float* __restrict__ wk,
                           const float* __restrict__ wv, float* __restrict__ dst)
{
    const int row = blockIdx.x;  // 0..3071
    const float* src = (row < Ee)     ? wq + (size_t)row * Ee
                     : (row < 2 * Ee) ? wk + (size_t)(row - Ee) * Ee
                                      : wv + (size_t)(row - 2 * Ee) * Ee;
    float4 v = ((const float4*)src)[threadIdx.x];
    ((float4*)(dst + (size_t)row * Ee))[threadIdx.x] =
        make_float4(to_tf32(v.x), to_tf32(v.y), to_tf32(v.z), to_tf32(v.w));
}
__global__ void pack_qkv_b(const float* __restrict__ bq, const float* __restrict__ bk,
                           const float* __restrict__ bv, float* __restrict__ dst)
{
    const float* s = blockIdx.x == 0 ? bq : blockIdx.x == 1 ? bk : bv;
    dst[blockIdx.x * Ee + threadIdx.x] = s[threadIdx.x];
}
__global__ void round_copy(const float* __restrict__ src, float* __restrict__ dst)
{
    size_t i = (size_t)blockIdx.x * blockDim.x + threadIdx.x;
    float4 v = ((const float4*)src)[i];
    ((float4*)dst)[i] = make_float4(to_tf32(v.x), to_tf32(v.y), to_tf32(v.z), to_tf32(v.w));
}

// ---------------- reductions ----------------
__device__ __forceinline__ float warpSum(float v) {
    #pragma unroll
    for (int o = 16; o; o >>= 1) v += __shfl_xor_sync(0xFFFFFFFFu, v, o);
    return v;
}
__device__ __forceinline__ float blockSum(float v, float* sh, float* bc) {
    int lane = threadIdx.x & 31, wid = threadIdx.x >> 5;
    v = warpSum(v);
    if (!lane) sh[wid] = v;
    __syncthreads();
    if (wid == 0) {
        v = (lane < 8) ? sh[lane] : 0.f;
        v = warpSum(v);
        if (!lane) *bc = v;
    }
    __syncthreads();
    return *bc;
}

// ---------------- LayerNorm (tf32-rounded output; feeds GEMMs only) ----------------
__global__ void ln_kernel(const float* __restrict__ x, const float* __restrict__ w,
                          const float* __restrict__ b, float* __restrict__ out)
{
    __shared__ float sh[32];
    __shared__ float bc;
    const int row = blockIdx.x, t = threadIdx.x;
    float4 v = *(const float4*)(x + (size_t)row * Ee + t * 4);
    float mean = blockSum(v.x + v.y + v.z + v.w, sh, &bc) * (1.f / Ee);
    float dx0 = v.x - mean, dx1 = v.y - mean, dx2 = v.z - mean, dx3 = v.w - mean;
    float var = blockSum(dx0*dx0 + dx1*dx1 + dx2*dx2 + dx3*dx3, sh, &bc) * (1.f / (Ee - 1));
    float r = 1.f / (sqrtf(var) + EPSc);
    float4 wv = *(const float4*)(w + t * 4);
    float4 bv = *(const float4*)(b + t * 4);
    float4 o;
    o.x = to_tf32(wv.x * dx0 * r + bv.x);
    o.y = to_tf32(wv.y * dx1 * r + bv.y);
    o.z = to_tf32(wv.z * dx2 * r + bv.z);
    o.w = to_tf32(wv.w * dx3 * r + bv.w);
    *(float4*)(out + (size_t)row * Ee + t * 4) = o;
}

// ---------------- flash attention: Br=64, Bc=64, 4 warps (inputs pre-rounded) ----------------
constexpr int FLD = 68;

__global__ void __launch_bounds__(128)
flash_kernel(const float* __restrict__ q, const float* __restrict__ k,
             const float* __restrict__ v, const int* __restrict__ mask,
             float* __restrict__ vals)
{
    extern __shared__ float sm[];
    float* Ksm = sm;
    float* Vsm = Ksm + 64 * FLD;
    float* Psm = Vsm + 64 * FLD;

    const int bh = blockIdx.y;
    const int b_ = bh >> 4, h_ = bh & 15;
    const int q0 = blockIdx.x * 64;
    const int tid = threadIdx.x, lane = tid & 31, w = tid >> 5;
    const int mi = lane >> 3, rr = lane & 7;

    const float* Qp = q + ((size_t)bh * Ss + q0) * Dd;
    const float* Kp = k + (size_t)bh * Ss * Dd;
    const float* Vp = v + (size_t)bh * Dd * Ss;

    #pragma unroll
    for (int i = tid; i < 64 * 16; i += 128) {
        int r = i >> 4, c4 = (i & 15) << 2;
        *(float4*)&Psm[r * FLD + c4] = *(const float4*)(Qp + (size_t)r * Dd + c4);
    }
    __syncthreads();
    uint32_t qa[8][4];
    #pragma unroll
    for (int ks = 0; ks < 8; ks++) {
        const float* p = &Psm[(w*16 + (mi & 1)*8 + rr) * FLD + ks*8 + ((mi >> 1) & 1)*4];
        ldsm4(qa[ks][0], qa[ks][1], qa[ks][2], qa[ks][3], p);
    }

    float oacc[8][4];
    #pragma unroll
    for (int i = 0; i < 8; i++)
        #pragma unroll
        for (int j = 0; j < 4; j++) oacc[i][j] = 0.f;
    float mrun0 = -1e30f, mrun1 = -1e30f, lrun0 = 0.f, lrun1 = 0.f;

    const int r0 = q0 + w*16 + (lane >> 2);
    const int* mrow0 = mask + ((size_t)b_ * Ss + r0) * Ss;
    const int* mrow1 = mrow0 + 8 * (size_t)Ss;

    for (int it = 0; it < Ss / 64; it++) {
        const int kv0 = it * 64;
        #pragma unroll
        for (int i = tid; i < 64 * 16; i += 128) {
            int r = i >> 4, c4 = (i & 15) << 2;
            *(float4*)&Ksm[r * FLD + c4] = *(const float4*)(Kp + (size_t)(kv0 + r) * Dd + c4);
        }
        #pragma unroll
        for (int i = tid; i < 64 * 16; i += 128) {
            int r = i >> 4, c4 = (i & 15) << 2;
            *(float4*)&Vsm[r * FLD + c4] = *(const float4*)(Vp + (size_t)r * Ss + kv0 + c4);
        }
        __syncthreads();

        float sacc[8][4];
        #pragma unroll
        for (int i = 0; i < 8; i++)
            #pragma unroll
            for (int j = 0; j < 4; j++) sacc[i][j] = 0.f;
        #pragma unroll
        for (int ks = 0; ks < 8; ks++) {
            uint32_t bf[8][2];
            #pragma unroll
            for (int pq = 0; pq < 4; pq++) {
                const float* p = &Ksm[(pq*16 + ((mi >> 1) & 1)*8 + rr) * FLD + ks*8 + (mi & 1)*4];
                ldsm4(bf[2*pq][0], bf[2*pq][1], bf[2*pq+1][0], bf[2*pq+1][1], p);
            }
            #pragma unroll
            for (int nt = 0; nt < 8; nt++) mma_tf32(sacc[nt], qa[ks], bf[nt]);
        }

        float ml0 = -1e30f, ml1 = -1e30f;
        #pragma unroll
        for (int nt = 0; nt < 8; nt++) {
            int c = kv0 + nt*8 + (lane & 3)*2;
            int2 ma = *(const int2*)(mrow0 + c);
            int2 mb = *(const int2*)(mrow1 + c);
            sacc[nt][0] = ma.x ? sacc[nt][0] * SCALE : -1e30f;
            sacc[nt][1] = ma.y ? sacc[nt][1] * SCALE : -1e30f;
            sacc[nt][2] = mb.x ? sacc[nt][2] * SCALE : -1e30f;
            sacc[nt][3] = mb.y ? sacc[nt][3] * SCALE : -1e30f;
            ml0 = fmaxf(ml0, fmaxf(sacc[nt][0], sacc[nt][1]));
            ml1 = fmaxf(ml1, fmaxf(sacc[nt][2], sacc[nt][3]));
        }
        ml0 = fmaxf(ml0, __shfl_xor_sync(0xFFFFFFFFu, ml0, 1));
        ml0 = fmaxf(ml0, __shfl_xor_sync(0xFFFFFFFFu, ml0, 2));
        ml1 = fmaxf(ml1, __shfl_xor_sync(0xFFFFFFFFu, ml1, 1));
        ml1 = fmaxf(ml1, __shfl_xor_sync(0xFFFFFFFFu, ml1, 2));
        float mn0 = fmaxf(mrun0, ml0), mn1 = fmaxf(mrun1, ml1);
        float f0 = __expf(mrun0 - mn0), f1 = __expf(mrun1 - mn1);
        float ps0 = 0.f, ps1 = 0.f;
        #pragma unroll
        for (int nt = 0; nt < 8; nt++) {
            sacc[nt][0] = __expf(sacc[nt][0] - mn0);
            sacc[nt][1] = __expf(sacc[nt][1] - mn0);
            sacc[nt][2] = __expf(sacc[nt][2] - mn1);
            sacc[nt][3] = __expf(sacc[nt][3] - mn1);
            ps0 += sacc[nt][0] + sacc[nt][1];
            ps1 += sacc[nt][2] + sacc[nt][3];
        }
        ps0 += __shfl_xor_sync(0xFFFFFFFFu, ps0, 1);
        ps0 += __shfl_xor_sync(0xFFFFFFFFu, ps0, 2);
        ps1 += __shfl_xor_sync(0xFFFFFFFFu, ps1, 1);
        ps1 += __shfl_xor_sync(0xFFFFFFFFu, ps1, 2);
        lrun0 = lrun0 * f0 + ps0; lrun1 = lrun1 * f1 + ps1;
        mrun0 = mn0; mrun1 = mn1;
        #pragma unroll
        for (int nt = 0; nt < 8; nt++) {
            oacc[nt][0] *= f0; oacc[nt][1] *= f0;
            oacc[nt][2] *= f1; oacc[nt][3] *= f1;
        }
        {
            int pr = w*16 + (lane >> 2);
            #pragma unroll
            for (int nt = 0; nt < 8; nt++) {
                int c = nt*8 + (lane & 3)*2;
                *(float2*)&Psm[pr * FLD + c] =
                    make_float2(to_tf32(sacc[nt][0]), to_tf32(sacc[nt][1]));
                *(float2*)&Psm[(pr + 8) * FLD + c] =
                    make_float2(to_tf32(sacc[nt][2]), to_tf32(sacc[nt][3]));
            }
        }
        __syncthreads();

        #pragma unroll
        for (int ks = 0; ks < 8; ks++) {
            uint32_t pa[4];
            {
                const float* p = &Psm[(w*16 + (mi & 1)*8 + rr) * FLD + ks*8 + ((mi >> 1) & 1)*4];
                ldsm4(pa[0], pa[1], pa[2], pa[3], p);
            }
            uint32_t bf[8][2];
            #pragma unroll
            for (int pq = 0; pq < 4; pq++) {
                const float* p = &Vsm[(pq*16 + ((mi >> 1) & 1)*8 + rr) * FLD + ks*8 + (mi & 1)*4];
                ldsm4(bf[2*pq][0], bf[2*pq][1], bf[2*pq+1][0], bf[2*pq+1][1], p);
            }
            #pragma unroll
            for (int nt = 0; nt < 8; nt++) mma_tf32(oacc[nt], pa, bf[nt]);
        }
        __syncthreads();
    }

    // normalize + round (vals feeds O-proj A-operand) + write
    float inv0 = 1.f / lrun0, inv1 = 1.f / lrun1;
    float* op = vals + ((size_t)b_ * Ss + r0) * Ee + h_ * Dd;
    #pragma unroll
    for (int nt = 0; nt < 8; nt++) {
        int c = nt*8 + (lane & 3)*2;
        *(float2*)(op + c) =
            make_float2(to_tf32(oacc[nt][0] * inv0), to_tf32(oacc[nt][1] * inv0));
        *(float2*)(op + (size_t)8 * Ee + c) =
            make_float2(to_tf32(oacc[nt][2] * inv1), to_tf32(oacc[nt][3] * inv1));
    }
}

// ---------------- tf32 dense GEMM: 3-stage cp.async, 1 sync/iter, pre-rounded inputs ----------------
// C[m,n] = sum_k A[m,k] * B[n,k]; B is [N,K] row-major; 256 threads, 128x128 tile,
// warp tile 32x64, 2 CTAs/SM. EPI: 1=bias+relu(+round), 2=bias+residual, 6=bias+QKV scatter(+round)
constexpr int GBM = 128, GBK = 32, GLD = 36;
constexpr int TILE_F = GBM * GLD;                    // 4608 floats
constexpr int NSTG = 3;
constexpr int GEMM_SMEM = 2 * NSTG * TILE_F * 4;     // 110592 bytes

template<int EPI>
__global__ void __launch_bounds__(256, 2)
gemm_tf32(const float* __restrict__ A, const float* __restrict__ Bm,
          const float* __restrict__ bias, const float* __restrict__ Res,
          float* __restrict__ C, int M, int N, int K)
{
    extern __shared__ float sms[];

    const int tid = threadIdx.x, lane = tid & 31, warp = tid >> 5;
    const int wm = warp >> 1, wn = warp & 1;          // 4(m) x 2(n); warp tile 32x64
    const int rowBase = blockIdx.y * GBM, colBase = blockIdx.x * GBM;
    const int l_r0 = tid >> 3, l_c = (tid & 7) << 2;  // +32 rows per chunk

    float acc[2][8][4];
    #pragma unroll
    for (int i = 0; i < 2; i++)
        #pragma unroll
        for (int j = 0; j < 8; j++)
            #pragma unroll
            for (int l = 0; l < 4; l++) acc[i][j][l] = 0.f;

    const int ntk = K / GBK;

    // issue all 8 cp.async for one K-tile into stage slot
    auto load_tile = [&](int tile, int slot) {
        const int k0 = tile * GBK;
        float* As = sms + slot * TILE_F;
        float* Bs = sms + (NSTG + slot) * TILE_F;
        #pragma unroll
        for (int i = 0; i < 4; i++) {
            const int r = l_r0 + i * 32;
            cp16(&As[r * GLD + l_c], A  + (size_t)(rowBase + r) * K + k0 + l_c);
            cp16(&Bs[r * GLD + l_c], Bm + (size_t)(colBase + r) * K + k0 + l_c);
        }
    };

    load_tile(0, 0); cp_commit();
    load_tile(1, 1); cp_commit();
    cp_wait<1>();          // tile 0 resident
    __syncthreads();

    const int mi = lane >> 3, rr = lane & 7;

    for (int kt = 0; kt < ntk; kt++) {
        const int slot = kt % NSTG;
        const float* Asb = sms + slot * TILE_F;
        const float* Bsb = sms + (NSTG + slot) * TILE_F;

        #pragma unroll
        for (int ks = 0; ks < 4; ks++) {
            const int ko = ks * 8;
            uint32_t a[2][4], b[8][2];
            #pragma unroll
            for (int mt = 0; mt < 2; mt++) {
                const float* p = &Asb[(wm*32 + mt*16 + (mi & 1)*8 + rr) * GLD + ko + ((mi >> 1) & 1)*4];
                ldsm4(a[mt][0], a[mt][1], a[mt][2], a[mt][3], p);
            }
            #pragma unroll
            for (int pq = 0; pq < 4; pq++) {
                const float* p = &Bsb[(wn*64 + pq*16 + ((mi >> 1) & 1)*8 + rr) * GLD + ko + (mi & 1)*4];
                ldsm4(b[2*pq][0], b[2*pq][1], b[2*pq+1][0], b[2*pq+1][1], p);
            }
            #pragma unroll
            for (int mt = 0; mt < 2; mt++)
                #pragma unroll
                for (int nt = 0; nt < 8; nt++)
                    mma_tf32(acc[mt][nt], a[mt], b[nt]);
        }

        // issue tile kt+2 into slot (kt+2)%3 == (kt-1)%3 — freed before last sync
        if (kt + 2 < ntk) load_tile(kt + 2, (kt + 2) % NSTG);
        cp_commit();
        cp_wait<1>();      // tile kt+1 resident
        __syncthreads();   // + WAR barrier for the slot written next iteration
    }

    // ---- epilogue ----
    #pragma unroll
    for (int mt = 0; mt < 2; mt++)
        #pragma unroll
        for (int half = 0; half < 2; half++) {
            const int row = rowBase + wm*32 + mt*16 + (lane >> 2) + half*8;
            #pragma unroll
            for (int nt = 0; nt < 8; nt++) {
                const int col = colBase + wn*64 + nt*8 + (lane & 3)*2;
                float v0 = acc[mt][nt][half*2 + 0];
                float v1 = acc[mt][nt][half*2 + 1];
                float2 bb = *(const float2*)(bias + col);
                v0 += bb.x; v1 += bb.y;
                if constexpr (EPI == 1) {
                    *(float2*)(C + (size_t)row * N + col) =
                        make_float2(to_tf32(fmaxf(v0, 0.f)), to_tf32(fmaxf(v1, 0.f)));
                } else if constexpr (EPI == 2) {
                    float2 r2 = *(const float2*)(Res + (size_t)row * N + col);
                    *(float2*)(C + (size_t)row * N + col) = make_float2(v0 + r2.x, v1 + r2.y);
                } else { // EPI == 6: QKV scatter, rounded (feeds flash)
                    int b_ = row / Ss, s_ = row - b_ * Ss;
                    v0 = to_tf32(v0); v1 = to_tf32(v1);
                    if (col < Ee) {
                        int h_ = col >> 6, d_ = col & 63;
                        *(float2*)(g_q + (((size_t)b_ * Hh + h_) * Ss + s_) * Dd + d_) = make_float2(v0, v1);
                    } else if (col < 2 * Ee) {
                        int c2 = col - Ee, h_ = c2 >> 6, d_ = c2 & 63;
                        *(float2*)(g_k + (((size_t)b_ * Hh + h_) * Ss + s_) * Dd + d_) = make_float2(v0, v1);
                    } else {
                        int c2 = col - 2 * Ee, h_ = c2 >> 6, d_ = c2 & 63;
                        float* pp = g_v + (((size_t)b_ * Hh + h_) * Dd + d_) * Ss + s_;
                        pp[0]  = v0;
                        pp[Ss] = v1;
                    }
                }
            }
        }
}

// ---------------- orchestration ----------------
extern "C" void kernel_launch(void* const* d_in, const int* in_sizes, int n_in,
                              void* d_out, int out_size)
{
    const float* x    = (const float*)d_in[0];
    const int*   mask = (const int*)  d_in[1];
    const float* wq   = (const float*)d_in[2];
    const float* bq   = (const float*)d_in[3];
    const float* wk   = (const float*)d_in[4];
    const float* bk   = (const float*)d_in[5];
    const float* wv   = (const float*)d_in[6];
    const float* bv   = (const float*)d_in[7];
    const float* wo   = (const float*)d_in[8];
    const float* bo   = (const float*)d_in[9];
    const float* w1   = (const float*)d_in[10];
    const float* b1   = (const float*)d_in[11];
    const float* w2   = (const float*)d_in[12];
    const float* b2   = (const float*)d_in[13];
    const float* ln1w = (const float*)d_in[14];
    const float* ln1b = (const float*)d_in[15];
    const float* ln2w = (const float*)d_in[16];
    const float* ln2b = (const float*)d_in[17];
    float* out = (float*)d_out;

    float *nx, *q, *k, *v, *vals, *x1, *hbuf, *wqkv, *bqkv, *rwo, *rw1, *rw2;
    cudaGetSymbolAddress((void**)&nx,   g_nx);
    cudaGetSymbolAddress((void**)&q,    g_q);
    cudaGetSymbolAddress((void**)&k,    g_k);
    cudaGetSymbolAddress((void**)&v,    g_v);
    cudaGetSymbolAddress((void**)&vals, g_vals);
    cudaGetSymbolAddress((void**)&x1,   g_x1);
    cudaGetSymbolAddress((void**)&hbuf, g_h);
    cudaGetSymbolAddress((void**)&wqkv, g_wqkv);
    cudaGetSymbolAddress((void**)&bqkv, g_bqkv);
    cudaGetSymbolAddress((void**)&rwo,  g_wo);
    cudaGetSymbolAddress((void**)&rw1,  g_w1);
    cudaGetSymbolAddress((void**)&rw2,  g_w2);

    const int flash_smem = 3 * 64 * FLD * sizeof(float);
    cudaFuncSetAttribute(flash_kernel, cudaFuncAttributeMaxDynamicSharedMemorySize, flash_smem);
    cudaFuncSetAttribute(gemm_tf32<1>, cudaFuncAttributeMaxDynamicSharedMemorySize, GEMM_SMEM);
    cudaFuncSetAttribute(gemm_tf32<2>, cudaFuncAttributeMaxDynamicSharedMemorySize, GEMM_SMEM);
    cudaFuncSetAttribute(gemm_tf32<6>, cudaFuncAttributeMaxDynamicSharedMemorySize, GEMM_SMEM);

    // 0. pack + round weights (~28us total)
    pack_qkv_w<<<3 * Ee, 256>>>(wq, wk, wv, wqkv);
    pack_qkv_b<<<3, Ee>>>(bq, bk, bv, bqkv);
    round_copy<<<(Ee * Ee) / 1024, 256>>>(wo, rwo);
    round_copy<<<(Ff * Ee) / 1024, 256>>>(w1, rw1);
    round_copy<<<(Ee * Ff) / 1024, 256>>>(w2, rw2);

    // 1. LN1 (rounded)
    ln_kernel<<<Mtok, 256>>>(x, ln1w, ln1b, nx);

    // 2. fused QKV projection -> q, k, v(transposed), rounded
    {
        dim3 g(3 * Ee / 128, Mtok / 128);
        gemm_tf32<6><<<g, 256, GEMM_SMEM>>>(nx, wqkv, bqkv, nullptr, nullptr, Mtok, 3 * Ee, Ee);
    }

    // 3. flash attention -> vals (rounded)
    {
        dim3 g(Ss / 64, Bb * Hh);
        flash_kernel<<<g, 128, flash_smem>>>(q, k, v, mask, vals);
    }

    // 4. O projection + residual -> x1 (fp32)
    {
        dim3 g(Ee / 128, Mtok / 128);
        gemm_tf32<2><<<g, 256, GEMM_SMEM>>>(vals, rwo, bo, x, x1, Mtok, Ee, Ee);
    }

    // 5. LN2 (rounded)
    ln_kernel<<<Mtok, 256>>>(x1, ln2w, ln2b, nx);

    // 6. FFN1 (relu, rounded) -> hbuf
    {
        dim3 g(Ff / 128, Mtok / 128);
        gemm_tf32<1><<<g, 256, GEMM_SMEM>>>(nx, rw1, b1, nullptr, hbuf, Mtok, Ff, Ee);
    }

    // 7. FFN2 + residual -> out (fp32)
    {
        dim3 g(Ee / 128, Mtok / 128);
        gemm_tf32<2><<<g, 256, GEMM_SMEM>>>(hbuf, rw2, b2, x1, out, Mtok, Ee, Ff);
    }
}